// round 11
// baseline (speedup 1.0000x reference)
#include <cuda_runtime.h>
#include <cuda_bf16.h>
#include <math.h>

typedef unsigned int u32;
typedef unsigned long long u64;

// ---------------- problem constants ----------------
#define B_   2
#define S_   2048
#define H_   2048
#define NH_  16
#define DH_  128
#define E_   6
#define R_   16
#define T_   (B_ * S_)            // 4096 tokens
#define SCALING_ 8.0f
#define INV_SQRT_DH 0.08838834764831845f

// tile: 128 rows x 32 bf16 = 64B/row, XOR-swizzled. 8KB per plane.
#define PLB 8192
#define STG_B (4 * PLB)           // Ahi, Alo, Bhi, Blo = 32KB
#define NSTG 3
#define SMEM_SZ (NSTG * STG_B)    // 96KB
#define FL_SMEM (11 * 2 * PLB)    // flash: Q(4) + P(4) + 3 B-stages = 176KB

// ---------------- scratch: fp32 ----------------
__device__ float g_vt[T_ * H_];
__device__ float g_xacat[T_ * 128];
__device__ float g_xao[T_ * 128];
__device__ float g_wcat[128 * H_];
__device__ float g_wcat2[128 * H_];
__device__ int   g_list_v[E_ * T_];
__device__ int   g_list_o[E_ * T_];
__device__ int   g_cnt_v[E_];
__device__ int   g_cnt_o[E_];
__device__ float g_wslot_v[T_ * 2];
__device__ float g_wslot_o[T_ * 2];

// ---------------- scratch: bf16 hi/lo planes (u32 = 2 bf16) ----------------
#define PT (T_ * H_ / 2)
#define PW (H_ * H_ / 2)
#define PE (E_ * H_ * H_ / 2)
#define PC (128 * H_ / 2)
__device__ u32 g_xs_h[PT],  g_xs_l[PT];
__device__ u32 g_qs_h[PT],  g_qs_l[PT];
__device__ u32 g_ks_h[PT],  g_ks_l[PT];
__device__ u32 g_cts_h[PT], g_cts_l[PT];
__device__ u32 g_vts_h[PT], g_vts_l[PT];
__device__ u32 g_wqs_h[PW], g_wqs_l[PW];
__device__ u32 g_wks_h[PW], g_wks_l[PW];
__device__ u32 g_vbs_h[PE], g_vbs_l[PE];
__device__ u32 g_obs_h[PE], g_obs_l[PE];
__device__ u32 g_wcs_h[PC], g_wcs_l[PC];
__device__ u32 g_wcs2_h[PC], g_wcs2_l[PC];

// ---------------- helpers ----------------
__device__ __forceinline__ u32 s2u(const void* p) {
    u32 a;
    asm("{ .reg .u64 t; cvta.to.shared.u64 t, %1; cvt.u32.u64 %0, t; }" : "=r"(a) : "l"(p));
    return a;
}
__device__ __forceinline__ u32 pack_bf2(float a, float b) {
    __nv_bfloat162 t = __floats2bfloat162_rn(a, b);
    return *reinterpret_cast<u32*>(&t);
}
__device__ __forceinline__ void split4(float4 v, u32& h0, u32& h1, u32& l0, u32& l1) {
    __nv_bfloat162 p0 = __floats2bfloat162_rn(v.x, v.y);
    __nv_bfloat162 p1 = __floats2bfloat162_rn(v.z, v.w);
    h0 = *reinterpret_cast<u32*>(&p0);
    h1 = *reinterpret_cast<u32*>(&p1);
    l0 = pack_bf2(v.x - __low2float(p0), v.y - __high2float(p0));
    l1 = pack_bf2(v.z - __low2float(p1), v.w - __high2float(p1));
}
__device__ __forceinline__ void split2(float a, float b, u32& h, u32& l) {
    __nv_bfloat162 p = __floats2bfloat162_rn(a, b);
    h = *reinterpret_cast<u32*>(&p);
    l = pack_bf2(a - __low2float(p), b - __high2float(p));
}
__device__ __forceinline__ void mma_bf16(float* c, u32 a0, u32 a1, u32 a2, u32 a3, u32 b0, u32 b1) {
    asm volatile(
        "mma.sync.aligned.m16n8k16.row.col.f32.bf16.bf16.f32 "
        "{%0,%1,%2,%3}, {%4,%5,%6,%7}, {%8,%9}, {%0,%1,%2,%3};"
        : "+f"(c[0]), "+f"(c[1]), "+f"(c[2]), "+f"(c[3])
        : "r"(a0), "r"(a1), "r"(a2), "r"(a3), "r"(b0), "r"(b1));
}
__device__ __forceinline__ void ldsm4(u32* r, u32 a) {
    asm volatile("ldmatrix.sync.aligned.m8n8.x4.shared.b16 {%0,%1,%2,%3}, [%4];"
        : "=r"(r[0]), "=r"(r[1]), "=r"(r[2]), "=r"(r[3]) : "r"(a));
}
__device__ __forceinline__ void cpa16(u32 dst, const void* src) {
    asm volatile("cp.async.ca.shared.global [%0], [%1], 16;" :: "r"(dst), "l"(src));
}
#define CPA_COMMIT() asm volatile("cp.async.commit_group;" ::: "memory")
#define CPA_WAIT1()  asm volatile("cp.async.wait_group 1;" ::: "memory")
#define CPA_WAIT0()  asm volatile("cp.async.wait_group 0;" ::: "memory")
// XOR swizzle: row 64B, seg = 16B chunk idx (0..3)
__device__ __forceinline__ u32 swb(int row, int seg) {
    return (u32)(row * 64 + ((seg ^ ((row >> 1) & 3)) * 16));
}

// one k16 MMA step over 128x128 tile (3-term bf16 split).
// aBase: A hi plane (lo at +PLB); bBase: B hi plane (lo at +PLB).
__device__ __forceinline__ void compute_k16(u32 aBase, u32 bBase, int ks,
                                            int wm, int wn, int lane,
                                            float (&acc)[4][4][4]) {
    int j = lane >> 3, r7 = lane & 7;
    int rowA = wm * 64 + (j & 1) * 8 + r7;
    int segA = ks * 2 + (j >> 1);
    u32 aH = aBase + swb(rowA, segA);
    u32 aL = aH + PLB;
    int rowB = wn * 32 + (j >> 1) * 8 + r7;
    int segB = ks * 2 + (j & 1);
    u32 bH = bBase + swb(rowB, segB);
    u32 bL = bH + PLB;

    u32 bh[2][4], bl[2][4], am[4][4];
    ldsm4(bh[0], bH); ldsm4(bh[1], bH + 1024);
    ldsm4(bl[0], bL); ldsm4(bl[1], bL + 1024);
#pragma unroll
    for (int mf = 0; mf < 4; mf++) ldsm4(am[mf], aH + mf * 1024);
#pragma unroll
    for (int mf = 0; mf < 4; mf++)
#pragma unroll
        for (int nf = 0; nf < 4; nf++) {
            const u32* b = &bh[nf >> 1][(nf & 1) * 2];
            mma_bf16(acc[mf][nf], am[mf][0], am[mf][1], am[mf][2], am[mf][3], b[0], b[1]);
        }
#pragma unroll
    for (int mf = 0; mf < 4; mf++)
#pragma unroll
        for (int nf = 0; nf < 4; nf++) {
            const u32* b = &bl[nf >> 1][(nf & 1) * 2];
            mma_bf16(acc[mf][nf], am[mf][0], am[mf][1], am[mf][2], am[mf][3], b[0], b[1]);
        }
#pragma unroll
    for (int mf = 0; mf < 4; mf++) ldsm4(am[mf], aL + mf * 1024);
#pragma unroll
    for (int mf = 0; mf < 4; mf++)
#pragma unroll
        for (int nf = 0; nf < 4; nf++) {
            const u32* b = &bh[nf >> 1][(nf & 1) * 2];
            mma_bf16(acc[mf][nf], am[mf][0], am[mf][1], am[mf][2], am[mf][3], b[0], b[1]);
        }
}

// ---------------- the one NT GEMM kernel ----------------
enum { M_XA = 1, M_MOE = 2, M_QKV = 6 };

typedef const __nv_bfloat16 cbf;

template <int MODE>
__global__ void __launch_bounds__(256) tc_gemm(
    cbf* Ah_, cbf* Al_, cbf* Bh_, cbf* Bl_,
    float* __restrict__ Cf,
    const float* __restrict__ Lab, const float* __restrict__ Lbb,
    const int* __restrict__ glist, const int* __restrict__ gcnt,
    const float* __restrict__ gw,
    const float* __restrict__ Lb2, const float* __restrict__ Lb3) {
    constexpr bool GATHER = (MODE == M_MOE);
    constexpr bool QKV = (MODE == M_QKV);
    constexpr bool LORA = (MODE == M_MOE || MODE == M_QKV);
    constexpr bool USETOK = (GATHER || QKV);
    extern __shared__ __align__(16) unsigned char dsm[];
    __shared__ int esm[128];
    __shared__ int tok[128];

    int tid = threadIdx.x;
    int m0 = blockIdx.y * 128, n0 = blockIdx.x * 128, z = blockIdx.z;

    cbf *pAh, *pAl, *pBh, *pBl;
    const float* La = nullptr;
    const float* Lb = nullptr;
    long lda, ldb, ldc = 0;
    int K, ldla = 0;
    size_t coff = 0;

    if constexpr (MODE == M_XA) {
        pAh = Ah_ + (size_t)m0 * H_; pAl = Al_ + (size_t)m0 * H_;
        pBh = Bh_; pBl = Bl_;
        coff = (size_t)m0 * 128;
        lda = ldb = H_; ldc = 128; K = H_;
    } else if constexpr (MODE == M_MOE) {
        pAh = Ah_; pAl = Al_;
        pBh = Bh_ + (size_t)z * H_ * H_ + (size_t)n0 * H_;
        pBl = Bl_ + (size_t)z * H_ * H_ + (size_t)n0 * H_;
        lda = ldb = H_; K = H_;
        La = Lab + z * R_; ldla = 128;
        Lb = Lbb + (size_t)z * H_ * R_ + (size_t)n0 * R_;
    } else {  // M_QKV
        pAh = (cbf*)g_xs_h; pAl = (cbf*)g_xs_l;
        size_t bo = (size_t)n0 * H_;
        if (z == 0)      { pBh = (cbf*)g_wqs_h + bo; pBl = (cbf*)g_wqs_l + bo; }
        else if (z == 1) { pBh = (cbf*)g_wks_h + bo; pBl = (cbf*)g_wks_l + bo; }
        else {
            size_t eo = (size_t)(z - 2) * H_ * H_;
            pBh = (cbf*)g_vbs_h + eo + bo; pBl = (cbf*)g_vbs_l + eo + bo;
        }
        lda = ldb = H_; K = H_; ldla = 128;
        La = g_xacat + (z == 0 ? 0 : (z == 1 ? 16 : 32 + (z - 2) * R_));
        Lb = (z == 0 ? Lbb : (z == 1 ? Lb2 : Lb3 + (size_t)(z - 2) * H_ * R_)) + (size_t)n0 * R_;
    }

    if constexpr (MODE == M_QKV) {
        if (z >= 2 && m0 >= gcnt[z - 2]) return;
        if (tid < 128) {
            if (z < 2) { tok[tid] = m0 + tid; esm[tid] = 0; }
            else {
                int count = gcnt[z - 2];
                int idx = m0 + tid;
                int en = (idx < count) ? glist[(z - 2) * T_ + idx] : -1;
                esm[tid] = en;
                tok[tid] = (en >= 0) ? (en >> 1) : 0;
            }
        }
        __syncthreads();
    } else if constexpr (GATHER) {
        int count = gcnt[z];
        if (m0 >= count) return;
        if (tid < 128) {
            int idx = m0 + tid;
            int en = (idx < count) ? glist[z * T_ + idx] : -1;
            esm[tid] = en;
            tok[tid] = (en >= 0) ? (en >> 1) : 0;
        }
        __syncthreads();
    }

    int wid = tid >> 5, lane = tid & 31;
    int wm = wid & 1, wn = wid >> 1, g = lane >> 2, tig = lane & 3;
    u32 smb = s2u(dsm);

    // per-thread loader pointers: rows cr and cr+64, seg = tid&3
    int cr = tid >> 2, seg = tid & 3;
    int ra0 = cr, ra1 = cr + 64;
    long ga0 = USETOK ? (long)tok[ra0] : ra0;
    long ga1 = USETOK ? (long)tok[ra1] : ra1;
    cbf* sAh0 = pAh + ga0 * lda + seg * 8;
    cbf* sAh1 = pAh + ga1 * lda + seg * 8;
    cbf* sAl0 = pAl + ga0 * lda + seg * 8;
    cbf* sAl1 = pAl + ga1 * lda + seg * 8;
    cbf* sBh0 = pBh + (long)ra0 * ldb + seg * 8;
    cbf* sBh1 = pBh + (long)ra1 * ldb + seg * 8;
    cbf* sBl0 = pBl + (long)ra0 * ldb + seg * 8;
    cbf* sBl1 = pBl + (long)ra1 * ldb + seg * 8;
    u32 d0 = swb(ra0, seg), d1 = swb(ra1, seg);

#define LOAD_STAGE(s, ktE) do { u32 st_ = smb + (s) * STG_B; int k_ = (ktE); \
    cpa16(st_ + d0, sAh0 + k_);            cpa16(st_ + d1, sAh1 + k_); \
    cpa16(st_ + PLB + d0, sAl0 + k_);      cpa16(st_ + PLB + d1, sAl1 + k_); \
    cpa16(st_ + 2 * PLB + d0, sBh0 + k_);  cpa16(st_ + 2 * PLB + d1, sBh1 + k_); \
    cpa16(st_ + 3 * PLB + d0, sBl0 + k_);  cpa16(st_ + 3 * PLB + d1, sBl1 + k_); } while (0)

    float acc[4][4][4];
#pragma unroll
    for (int a = 0; a < 4; a++)
#pragma unroll
        for (int b = 0; b < 4; b++)
#pragma unroll
            for (int c = 0; c < 4; c++) acc[a][b][c] = 0.f;

    int nk = K / 32;
    LOAD_STAGE(0, 0);  CPA_COMMIT();
    LOAD_STAGE(1, 32); CPA_COMMIT();

    for (int it = 0; it < nk; it++) {
        CPA_WAIT1();
        __syncthreads();
        // prefetch FIRST (safe: sync(it) implies compute(it-1) done), then compute
        if (it + 2 < nk) LOAD_STAGE((it + 2) % NSTG, (it + 2) * 32);
        CPA_COMMIT();
        u32 stg = smb + (it % NSTG) * STG_B;
        compute_k16(stg, stg + 2 * PLB, 0, wm, wn, lane, acc);
        compute_k16(stg, stg + 2 * PLB, 1, wm, wn, lane, acc);
    }
    CPA_WAIT0();
    __syncthreads();

    if constexpr (LORA) {
        // one extra k16: A = SCALING*La (fp32, rows via tok), B = Lb (fp32); segs 0..1
#pragma unroll
        for (int i = 0; i < 2; i++) {
            int f = tid + i * 256;
            int row = f >> 2, kc = (f & 3) * 4;
            size_t ro = (size_t)tok[row] * ldla;
            float4 v = *(const float4*)(La + ro + kc);
            v.x *= SCALING_; v.y *= SCALING_; v.z *= SCALING_; v.w *= SCALING_;
            u32 h0, h1, l0, l1;
            split4(v, h0, h1, l0, l1);
            u32 off = smb + swb(row, kc >> 3) + (kc & 7) * 2;
            asm volatile("st.shared.v2.u32 [%0], {%1,%2};" :: "r"(off), "r"(h0), "r"(h1));
            asm volatile("st.shared.v2.u32 [%0], {%1,%2};" :: "r"(off + PLB), "r"(l0), "r"(l1));
            float4 u = *(const float4*)(Lb + (size_t)row * R_ + kc);
            split4(u, h0, h1, l0, l1);
            asm volatile("st.shared.v2.u32 [%0], {%1,%2};" :: "r"(off + 2 * PLB), "r"(h0), "r"(h1));
            asm volatile("st.shared.v2.u32 [%0], {%1,%2};" :: "r"(off + 3 * PLB), "r"(l0), "r"(l1));
        }
        __syncthreads();
        compute_k16(smb, smb + 2 * PLB, 0, wm, wn, lane, acc);
    }

    // ---------------- epilogues ----------------
    if constexpr (MODE == M_QKV) {
        if (z < 2) {
            u32* ch = (z == 0) ? g_qs_h : g_ks_h;
            u32* cl = (z == 0) ? g_qs_l : g_ks_l;
            size_t co = (size_t)m0 * H_ + n0;
#pragma unroll
            for (int mf = 0; mf < 4; mf++) {
#pragma unroll
                for (int half = 0; half < 2; half++) {
                    int m = wm * 64 + mf * 16 + g + half * 8;
#pragma unroll
                    for (int nf = 0; nf < 4; nf++) {
                        int n = wn * 32 + nf * 8 + tig * 2;
                        u32 h, l;
                        split2(acc[mf][nf][half * 2 + 0], acc[mf][nf][half * 2 + 1], h, l);
                        size_t ix = (co + (size_t)m * H_ + n) >> 1;
                        ch[ix] = h;
                        cl[ix] = l;
                    }
                }
            }
        } else {
#pragma unroll
            for (int mf = 0; mf < 4; mf++) {
#pragma unroll
                for (int half = 0; half < 2; half++) {
                    int lr = wm * 64 + mf * 16 + g + half * 8;
                    int en = esm[lr];
                    if (en < 0) continue;
                    float w = gw[en];
                    int t = en >> 1;
                    int b = t >> 11, sI = t & (S_ - 1);
#pragma unroll
                    for (int nf = 0; nf < 4; nf++) {
                        int n = n0 + wn * 32 + nf * 8 + tig * 2;
                        atomicAdd(&g_vt[((size_t)(b * H_ + n)) * S_ + sI],
                                  w * acc[mf][nf][half * 2 + 0]);
                        atomicAdd(&g_vt[((size_t)(b * H_ + n + 1)) * S_ + sI],
                                  w * acc[mf][nf][half * 2 + 1]);
                    }
                }
            }
        }
    } else if constexpr (GATHER) {
#pragma unroll
        for (int mf = 0; mf < 4; mf++) {
#pragma unroll
            for (int half = 0; half < 2; half++) {
                int lr = wm * 64 + mf * 16 + g + half * 8;
                int en = esm[lr];
                if (en < 0) continue;
                float w = gw[en];
                int t = en >> 1;
#pragma unroll
                for (int nf = 0; nf < 4; nf++) {
                    int n = n0 + wn * 32 + nf * 8 + tig * 2;
                    float* p = Cf + (size_t)t * H_ + n;
                    atomicAdd(p, w * acc[mf][nf][half * 2 + 0]);
                    atomicAdd(p + 1, w * acc[mf][nf][half * 2 + 1]);
                }
            }
        }
    } else {  // M_XA: fp32 out
        float* C = Cf + coff;
#pragma unroll
        for (int mf = 0; mf < 4; mf++) {
#pragma unroll
            for (int half = 0; half < 2; half++) {
                int m = wm * 64 + mf * 16 + g + half * 8;
#pragma unroll
                for (int nf = 0; nf < 4; nf++) {
                    int n = wn * 32 + nf * 8 + tig * 2;
                    float2 v = {acc[mf][nf][half * 2 + 0], acc[mf][nf][half * 2 + 1]};
                    *(float2*)(C + (size_t)m * ldc + n) = v;
                }
            }
        }
    }
#undef LOAD_STAGE
}

// ---------------- flash attention: scores+softmax+ctx fused ----------------
__global__ void __launch_bounds__(256) flash_kernel(const float* __restrict__ amask) {
    extern __shared__ __align__(16) unsigned char dsm[];
    __shared__ float s_L[128];
    __shared__ float s_mask[S_];

    int tid = threadIdx.x;
    int z = blockIdx.z, q0 = blockIdx.y * 128;
    int bb = z >> 4, h = z & 15;
    u32 smb = s2u(dsm);
    u32 Qb = smb;                       // 4 chunks x (hi+lo) = 64KB
    u32 Pb = smb + 4 * 2 * PLB;         // 64KB
    u32 STb = smb + 8 * 2 * PLB;        // 3 stages x 16KB

    int wid = tid >> 5, lane = tid & 31;
    int wm = wid & 1, wn = wid >> 1, g = lane >> 2, tig = lane & 3;
    int cr = tid >> 2, seg = tid & 3;
    u32 d0 = swb(cr, seg), d1 = swb(cr + 64, seg);

    // Q tile load (resident)
    {
        size_t o0 = ((size_t)(bb * S_ + q0 + cr)) * H_ + h * DH_ + seg * 8;
        size_t o1 = ((size_t)(bb * S_ + q0 + cr + 64)) * H_ + h * DH_ + seg * 8;
        cbf* qh0 = (cbf*)g_qs_h + o0; cbf* qh1 = (cbf*)g_qs_h + o1;
        cbf* ql0 = (cbf*)g_qs_l + o0; cbf* ql1 = (cbf*)g_qs_l + o1;
#pragma unroll
        for (int c = 0; c < 4; c++) {
            u32 qb = Qb + c * 2 * PLB;
            cpa16(qb + d0, qh0 + c * 32); cpa16(qb + d1, qh1 + c * 32);
            cpa16(qb + PLB + d0, ql0 + c * 32); cpa16(qb + PLB + d1, ql1 + c * 32);
        }
        CPA_COMMIT();
    }
    for (int i = tid; i < S_; i += 256)
        s_mask[i] = (1.f - amask[(size_t)bb * S_ + i]) * (-10000.f);
    if (tid < 128) s_L[tid] = 0.f;

    float accC[4][4][4];
#pragma unroll
    for (int a = 0; a < 4; a++)
#pragma unroll
        for (int b = 0; b < 4; b++)
#pragma unroll
            for (int c = 0; c < 4; c++) accC[a][b][c] = 0.f;

#define LDB(s, koff) do { u32 st_ = STb + (s) * 2 * PLB; int k_ = (koff); \
    cpa16(st_ + d0, bh0 + k_);       cpa16(st_ + d1, bh1 + k_); \
    cpa16(st_ + PLB + d0, bl0 + k_); cpa16(st_ + PLB + d1, bl1 + k_); } while (0)

    for (int j = 0; j < S_ / 128; j++) {
        // ---- phase A: S = Q @ K^T over this kv tile ----
        size_t ko0 = ((size_t)(bb * S_ + j * 128 + cr)) * H_ + h * DH_ + seg * 8;
        size_t ko1 = ((size_t)(bb * S_ + j * 128 + cr + 64)) * H_ + h * DH_ + seg * 8;
        cbf* bh0 = (cbf*)g_ks_h + ko0; cbf* bh1 = (cbf*)g_ks_h + ko1;
        cbf* bl0 = (cbf*)g_ks_l + ko0; cbf* bl1 = (cbf*)g_ks_l + ko1;
        __syncthreads();   // protect stage/P reuse from previous tile
        LDB(0, 0);  CPA_COMMIT();
        LDB(1, 32); CPA_COMMIT();
        float accS[4][4][4];
#pragma unroll
        for (int a = 0; a < 4; a++)
#pragma unroll
            for (int b = 0; b < 4; b++)
#pragma unroll
                for (int c = 0; c < 4; c++) accS[a][b][c] = 0.f;
#pragma unroll
        for (int c = 0; c < 4; c++) {
            CPA_WAIT1();
            __syncthreads();
            if (c < 2) LDB((c + 2) % 3, (c + 2) * 32);
            CPA_COMMIT();
            u32 a = Qb + c * 2 * PLB, b = STb + (c % 3) * 2 * PLB;
            compute_k16(a, b, 0, wm, wn, lane, accS);
            compute_k16(a, b, 1, wm, wn, lane, accS);
        }
        // ---- phase B: exp + mask -> P smem, row sums ----
#pragma unroll
        for (int mf = 0; mf < 4; mf++) {
#pragma unroll
            for (int half = 0; half < 2; half++) {
                int r = wm * 64 + mf * 16 + g + half * 8;
                float rs = 0.f;
#pragma unroll
                for (int nf = 0; nf < 4; nf++) {
                    int cn = wn * 32 + nf * 8 + tig * 2;
                    float e0 = __expf(accS[mf][nf][half * 2 + 0] * INV_SQRT_DH + s_mask[j * 128 + cn]);
                    float e1 = __expf(accS[mf][nf][half * 2 + 1] * INV_SQRT_DH + s_mask[j * 128 + cn + 1]);
                    rs += e0 + e1;
                    u32 hh, ll;
                    split2(e0, e1, hh, ll);
                    int chunk = cn >> 5, kc = cn & 31;
                    u32 off = Pb + chunk * 2 * PLB + swb(r, kc >> 3) + (kc & 7) * 2;
                    asm volatile("st.shared.b32 [%0], %1;" :: "r"(off), "r"(hh));
                    asm volatile("st.shared.b32 [%0], %1;" :: "r"(off + PLB), "r"(ll));
                }
                rs += __shfl_xor_sync(0xffffffffu, rs, 1);
                rs += __shfl_xor_sync(0xffffffffu, rs, 2);
                if (tig == 0) atomicAdd(&s_L[r], rs);
            }
        }
        __syncthreads();   // P complete before ctx MMAs read it
        // ---- phase D: C += P @ Vt over this kv tile ----
        size_t vo0 = ((size_t)((bb * NH_ + h) * DH_ + cr)) * S_ + j * 128 + seg * 8;
        size_t vo1 = ((size_t)((bb * NH_ + h) * DH_ + cr + 64)) * S_ + j * 128 + seg * 8;
        bh0 = (cbf*)g_vts_h + vo0; bh1 = (cbf*)g_vts_h + vo1;
        bl0 = (cbf*)g_vts_l + vo0; bl1 = (cbf*)g_vts_l + vo1;
        LDB(0, 0);  CPA_COMMIT();
        LDB(1, 32); CPA_COMMIT();
#pragma unroll
        for (int c = 0; c < 4; c++) {
            CPA_WAIT1();
            __syncthreads();
            if (c < 2) LDB((c + 2) % 3, (c + 2) * 32);
            CPA_COMMIT();
            u32 a = Pb + c * 2 * PLB, b = STb + (c % 3) * 2 * PLB;
            compute_k16(a, b, 0, wm, wn, lane, accC);
            compute_k16(a, b, 1, wm, wn, lane, accC);
        }
    }
    __syncthreads();

    // ---- epilogue: normalize by row sums, write cts planes ----
    size_t coff = ((size_t)(bb * S_ + q0)) * H_ + h * DH_;
#pragma unroll
    for (int mf = 0; mf < 4; mf++) {
#pragma unroll
        for (int half = 0; half < 2; half++) {
            int m = wm * 64 + mf * 16 + g + half * 8;
            float iv = 1.f / s_L[m];
#pragma unroll
            for (int nf = 0; nf < 4; nf++) {
                int n = wn * 32 + nf * 8 + tig * 2;
                u32 hh, ll;
                split2(accC[mf][nf][half * 2 + 0] * iv, accC[mf][nf][half * 2 + 1] * iv, hh, ll);
                size_t ix = (coff + (size_t)m * H_ + n) >> 1;
                g_cts_h[ix] = hh;
                g_cts_l[ix] = ll;
            }
        }
    }
#undef LDB
}

// ---------------- split fp32 -> bf16 hi/lo planes ----------------
__global__ void split_kernel(const float4* __restrict__ src, u32* __restrict__ hi,
                             u32* __restrict__ lo, int n4) {
    for (int i = blockIdx.x * blockDim.x + threadIdx.x; i < n4; i += gridDim.x * blockDim.x) {
        float4 v = src[i];
        u32 h0, h1, l0, l1;
        split4(v, h0, h1, l0, l1);
        *(uint2*)&hi[(size_t)i * 2] = make_uint2(h0, h1);
        *(uint2*)&lo[(size_t)i * 2] = make_uint2(l0, l1);
    }
}

// ---------------- init counts ----------------
__global__ void init_counts_kernel() {
    if (threadIdx.x < E_) {
        g_cnt_v[threadIdx.x] = 0;
        g_cnt_o[threadIdx.x] = 0;
    }
}

// ---------------- routing ----------------
__global__ void routing_kernel(const float* __restrict__ x,
                               const float* __restrict__ gv,
                               const float* __restrict__ go) {
    int t = blockIdx.x;
    const float* xt = x + (size_t)t * H_;
    float pv[E_], po[E_];
#pragma unroll
    for (int e = 0; e < E_; e++) { pv[e] = 0.f; po[e] = 0.f; }
    for (int k = threadIdx.x; k < H_; k += 128) {
        float xv = xt[k];
#pragma unroll
        for (int e = 0; e < E_; e++) {
            pv[e] += xv * gv[e * H_ + k];
            po[e] += xv * go[e * H_ + k];
        }
    }
    __shared__ float red[2 * E_][128];
#pragma unroll
    for (int e = 0; e < E_; e++) {
        red[e][threadIdx.x] = pv[e];
        red[E_ + e][threadIdx.x] = po[e];
    }
    __syncthreads();
    if (threadIdx.x < 2 * E_) {
        float s = 0.f;
        for (int i = 0; i < 128; i++) s += red[threadIdx.x][i];
        red[threadIdx.x][0] = s;
    }
    __syncthreads();
    if (threadIdx.x < 2) {
        bool isO = (threadIdx.x == 1);
        float sc[E_];
#pragma unroll
        for (int e = 0; e < E_; e++) {
            float d = red[(isO ? E_ : 0) + e][0];
            sc[e] = 1.f / (1.f + expf(-d));
        }
        int e0 = 0;
        for (int e = 1; e < E_; e++) if (sc[e] > sc[e0]) e0 = e;
        int e1 = -1;
        for (int e = 0; e < E_; e++) {
            if (e == e0) continue;
            if (e1 < 0 || sc[e] > sc[e1]) e1 = e;
        }
        float t1 = expf(sc[e1] - sc[e0]);
        float w0 = 1.f / (1.f + t1);
        float w1 = t1 / (1.f + t1);
        if (!isO) {
            g_wslot_v[t * 2 + 0] = w0;
            g_wslot_v[t * 2 + 1] = w1;
            int p0 = atomicAdd(&g_cnt_v[e0], 1); g_list_v[e0 * T_ + p0] = t * 2 + 0;
            int p1 = atomicAdd(&g_cnt_v[e1], 1); g_list_v[e1 * T_ + p1] = t * 2 + 1;
        } else {
            g_wslot_o[t * 2 + 0] = w0;
            g_wslot_o[t * 2 + 1] = w1;
            int p0 = atomicAdd(&g_cnt_o[e0], 1); g_list_o[e0 * T_ + p0] = t * 2 + 0;
            int p1 = atomicAdd(&g_cnt_o[e1], 1); g_list_o[e1 * T_ + p1] = t * 2 + 1;
        }
    }
}

// ---------------- launcher ----------------
extern "C" void kernel_launch(void* const* d_in, const int* in_sizes, int n_in,
                              void* d_out, int out_size) {
    const float* x      = (const float*)d_in[0];
    const float* amask  = (const float*)d_in[1];
    const float* wq     = (const float*)d_in[2];
    const float* wk     = (const float*)d_in[3];
    const float* q_a    = (const float*)d_in[4];
    const float* q_b    = (const float*)d_in[5];
    const float* k_a    = (const float*)d_in[6];
    const float* k_b    = (const float*)d_in[7];
    const float* gv     = (const float*)d_in[8];
    const float* go     = (const float*)d_in[9];
    const float* v_base = (const float*)d_in[10];
    const float* v_a    = (const float*)d_in[11];
    const float* v_b    = (const float*)d_in[12];
    const float* o_base = (const float*)d_in[13];
    const float* o_a    = (const float*)d_in[14];
    const float* o_b    = (const float*)d_in[15];
    float* out = (float*)d_out;

#define SYM(v, s) void* v; cudaGetSymbolAddress(&v, s)
    SYM(p_vt, g_vt); SYM(p_xacat, g_xacat); SYM(p_xao, g_xao);
    SYM(p_wcat, g_wcat); SYM(p_wcat2, g_wcat2);
    SYM(p_list_v, g_list_v); SYM(p_list_o, g_list_o);
    SYM(p_cnt_v, g_cnt_v); SYM(p_cnt_o, g_cnt_o);
    SYM(p_ws_v, g_wslot_v); SYM(p_ws_o, g_wslot_o);
    SYM(xs_h, g_xs_h); SYM(xs_l, g_xs_l);
    SYM(cts_h, g_cts_h); SYM(cts_l, g_cts_l);
    SYM(vts_h, g_vts_h); SYM(vts_l, g_vts_l);
    SYM(wqs_h, g_wqs_h); SYM(wqs_l, g_wqs_l);
    SYM(wks_h, g_wks_h); SYM(wks_l, g_wks_l);
    SYM(vbs_h, g_vbs_h); SYM(vbs_l, g_vbs_l);
    SYM(obs_h, g_obs_h); SYM(obs_l, g_obs_l);
    SYM(wcs_h, g_wcs_h); SYM(wcs_l, g_wcs_l);
    SYM(wcs2_h, g_wcs2_h); SYM(wcs2_l, g_wcs2_l);
#undef SYM

    cudaFuncSetAttribute(tc_gemm<M_XA>,  cudaFuncAttributeMaxDynamicSharedMemorySize, SMEM_SZ);
    cudaFuncSetAttribute(tc_gemm<M_MOE>, cudaFuncAttributeMaxDynamicSharedMemorySize, SMEM_SZ);
    cudaFuncSetAttribute(tc_gemm<M_QKV>, cudaFuncAttributeMaxDynamicSharedMemorySize, SMEM_SZ);
    cudaFuncSetAttribute(flash_kernel,   cudaFuncAttributeMaxDynamicSharedMemorySize, FL_SMEM);

    // LoRA-A weight concats (fp32)
    cudaMemcpyAsync((float*)p_wcat,           q_a, sizeof(float) * R_ * H_,      cudaMemcpyDeviceToDevice);
    cudaMemcpyAsync((float*)p_wcat + 16 * H_, k_a, sizeof(float) * R_ * H_,      cudaMemcpyDeviceToDevice);
    cudaMemcpyAsync((float*)p_wcat + 32 * H_, v_a, sizeof(float) * E_ * R_ * H_, cudaMemcpyDeviceToDevice);
    cudaMemcpyAsync((float*)p_wcat2,          o_a, sizeof(float) * E_ * R_ * H_, cudaMemcpyDeviceToDevice);

    cudaMemsetAsync(p_vt, 0, sizeof(float) * (size_t)T_ * H_);
    cudaMemsetAsync(out, 0, sizeof(float) * (size_t)T_ * H_);
    init_counts_kernel<<<1, 32>>>();
    routing_kernel<<<T_, 128>>>(x, gv, go);

    // splits: inputs + weights
    split_kernel<<<1024, 256>>>((const float4*)x,      (u32*)xs_h,  (u32*)xs_l,  T_ * H_ / 4);
    split_kernel<<<1024, 256>>>((const float4*)wq,     (u32*)wqs_h, (u32*)wqs_l, H_ * H_ / 4);
    split_kernel<<<1024, 256>>>((const float4*)wk,     (u32*)wks_h, (u32*)wks_l, H_ * H_ / 4);
    split_kernel<<<2048, 256>>>((const float4*)v_base, (u32*)vbs_h, (u32*)vbs_l, E_ * H_ * H_ / 4);
    split_kernel<<<2048, 256>>>((const float4*)o_base, (u32*)obs_h, (u32*)obs_l, E_ * H_ * H_ / 4);
    split_kernel<<<256, 256>>>((const float4*)p_wcat,  (u32*)wcs_h, (u32*)wcs_l, 128 * H_ / 4);
    split_kernel<<<256, 256>>>((const float4*)p_wcat2, (u32*)wcs2_h, (u32*)wcs2_l, 128 * H_ / 4);

    // XA: xacat = x @ wcat^T (fp32 out)
    tc_gemm<M_XA><<<dim3(1, T_ / 128), 256, SMEM_SZ>>>(
        (cbf*)xs_h, (cbf*)xs_l, (cbf*)wcs_h, (cbf*)wcs_l,
        (float*)p_xacat, nullptr, nullptr, nullptr, nullptr, nullptr, nullptr, nullptr);

    // fused Q-proj (z=0), K-proj (z=1), V-MoE (z=2..7)
    tc_gemm<M_QKV><<<dim3(H_ / 128, T_ / 128, 2 + E_), 256, SMEM_SZ>>>(
        nullptr, nullptr, nullptr, nullptr,
        nullptr,
        nullptr, q_b,
        (const int*)p_list_v, (const int*)p_cnt_v, (const float*)p_ws_v,
        k_b, v_b);

    // split vt
    split_kernel<<<1024, 256>>>((const float4*)p_vt, (u32*)vts_h, (u32*)vts_l, T_ * H_ / 4);

    // fused attention (scores + softmax + ctx)
    flash_kernel<<<dim3(1, S_ / 128, B_ * NH_), 256, FL_SMEM>>>(amask);

    // O path
    tc_gemm<M_XA><<<dim3(1, T_ / 128), 256, SMEM_SZ>>>(
        (cbf*)cts_h, (cbf*)cts_l, (cbf*)wcs2_h, (cbf*)wcs2_l,
        (float*)p_xao, nullptr, nullptr, nullptr, nullptr, nullptr, nullptr, nullptr);
    tc_gemm<M_MOE><<<dim3(H_ / 128, T_ / 128, E_), 256, SMEM_SZ>>>(
        (cbf*)cts_h, (cbf*)cts_l, (cbf*)obs_h, (cbf*)obs_l,
        out, (const float*)p_xao, o_b,
        (const int*)p_list_o, (const int*)p_cnt_o, (const float*)p_ws_o,
        nullptr, nullptr);
}

// round 12
// speedup vs baseline: 1.0147x; 1.0147x over previous
#include <cuda_runtime.h>
#include <cuda_bf16.h>
#include <math.h>

typedef unsigned int u32;
typedef unsigned long long u64;

// ---------------- problem constants ----------------
#define B_   2
#define S_   2048
#define H_   2048
#define NH_  16
#define DH_  128
#define E_   6
#define R_   16
#define T_   (B_ * S_)            // 4096 tokens
#define SCALING_ 8.0f
#define INV_SQRT_DH 0.08838834764831845f

// tile: 128 rows x 32 bf16 = 64B/row, XOR-swizzled. 8KB per plane.
#define PLB 8192
#define STG_B (4 * PLB)           // Ahi, Alo, Bhi, Blo = 32KB
#define NSTG 3
#define SMEM_SZ (NSTG * STG_B)    // 96KB

// ---------------- scratch: fp32 ----------------
__device__ float g_vt[T_ * H_];        // V untransposed [t][n] (atomic accum)
__device__ float g_L[B_ * NH_ * S_];   // unnormalized softmax row sums
__device__ float g_xacat[T_ * 128];
__device__ float g_xao[T_ * 128];
__device__ float g_wcat[128 * H_];
__device__ float g_wcat2[128 * H_];
__device__ int   g_list_v[E_ * T_];
__device__ int   g_list_o[E_ * T_];
__device__ int   g_cnt_v[E_];
__device__ int   g_cnt_o[E_];
__device__ float g_wslot_v[T_ * 2];
__device__ float g_wslot_o[T_ * 2];

// ---------------- scratch: bf16 hi/lo planes (u32 = 2 bf16) ----------------
#define PT (T_ * H_ / 2)
#define PW (H_ * H_ / 2)
#define PE (E_ * H_ * H_ / 2)
#define PC (128 * H_ / 2)
__device__ u32 g_xs_h[PT],  g_xs_l[PT];
__device__ u32 g_qs_h[PT],  g_qs_l[PT];
__device__ u32 g_ks_h[PT],  g_ks_l[PT];
__device__ u32 g_cts_h[PT], g_cts_l[PT];
__device__ u32 g_vts_h[PT], g_vts_l[PT];   // V transposed planes [b*H+n][S]
__device__ u32 g_Ps_h[(size_t)B_ * NH_ * S_ * S_ / 2];
__device__ u32 g_Ps_l[(size_t)B_ * NH_ * S_ * S_ / 2];
__device__ u32 g_wqs_h[PW], g_wqs_l[PW];
__device__ u32 g_wks_h[PW], g_wks_l[PW];
__device__ u32 g_vbs_h[PE], g_vbs_l[PE];
__device__ u32 g_obs_h[PE], g_obs_l[PE];
__device__ u32 g_wcs_h[PC], g_wcs_l[PC];
__device__ u32 g_wcs2_h[PC], g_wcs2_l[PC];

// ---------------- helpers ----------------
__device__ __forceinline__ u32 s2u(const void* p) {
    u32 a;
    asm("{ .reg .u64 t; cvta.to.shared.u64 t, %1; cvt.u32.u64 %0, t; }" : "=r"(a) : "l"(p));
    return a;
}
__device__ __forceinline__ u32 pack_bf2(float a, float b) {
    __nv_bfloat162 t = __floats2bfloat162_rn(a, b);
    return *reinterpret_cast<u32*>(&t);
}
__device__ __forceinline__ void split4(float4 v, u32& h0, u32& h1, u32& l0, u32& l1) {
    __nv_bfloat162 p0 = __floats2bfloat162_rn(v.x, v.y);
    __nv_bfloat162 p1 = __floats2bfloat162_rn(v.z, v.w);
    h0 = *reinterpret_cast<u32*>(&p0);
    h1 = *reinterpret_cast<u32*>(&p1);
    l0 = pack_bf2(v.x - __low2float(p0), v.y - __high2float(p0));
    l1 = pack_bf2(v.z - __low2float(p1), v.w - __high2float(p1));
}
__device__ __forceinline__ void split2(float a, float b, u32& h, u32& l) {
    __nv_bfloat162 p = __floats2bfloat162_rn(a, b);
    h = *reinterpret_cast<u32*>(&p);
    l = pack_bf2(a - __low2float(p), b - __high2float(p));
}
__device__ __forceinline__ void mma_bf16(float* c, u32 a0, u32 a1, u32 a2, u32 a3, u32 b0, u32 b1) {
    asm volatile(
        "mma.sync.aligned.m16n8k16.row.col.f32.bf16.bf16.f32 "
        "{%0,%1,%2,%3}, {%4,%5,%6,%7}, {%8,%9}, {%0,%1,%2,%3};"
        : "+f"(c[0]), "+f"(c[1]), "+f"(c[2]), "+f"(c[3])
        : "r"(a0), "r"(a1), "r"(a2), "r"(a3), "r"(b0), "r"(b1));
}
__device__ __forceinline__ void ldsm4(u32* r, u32 a) {
    asm volatile("ldmatrix.sync.aligned.m8n8.x4.shared.b16 {%0,%1,%2,%3}, [%4];"
        : "=r"(r[0]), "=r"(r[1]), "=r"(r[2]), "=r"(r[3]) : "r"(a));
}
__device__ __forceinline__ void cpa16(u32 dst, const void* src) {
    asm volatile("cp.async.ca.shared.global [%0], [%1], 16;" :: "r"(dst), "l"(src));
}
#define CPA_COMMIT() asm volatile("cp.async.commit_group;" ::: "memory")
#define CPA_WAIT1()  asm volatile("cp.async.wait_group 1;" ::: "memory")
#define CPA_WAIT0()  asm volatile("cp.async.wait_group 0;" ::: "memory")
// XOR swizzle: row 64B, seg = 16B chunk idx (0..3)
__device__ __forceinline__ u32 swb(int row, int seg) {
    return (u32)(row * 64 + ((seg ^ ((row >> 1) & 3)) * 16));
}

// one k16 MMA step over 128x128 tile (3-term bf16 split), stage base = stg
__device__ __forceinline__ void compute_k16(u32 stg, int ks, int wm, int wn, int lane,
                                            float (&acc)[4][4][4]) {
    int j = lane >> 3, r7 = lane & 7;
    int rowA = wm * 64 + (j & 1) * 8 + r7;
    int segA = ks * 2 + (j >> 1);
    u32 aH = stg + swb(rowA, segA);
    u32 aL = aH + PLB;
    int rowB = wn * 32 + (j >> 1) * 8 + r7;
    int segB = ks * 2 + (j & 1);
    u32 bH = stg + 2 * PLB + swb(rowB, segB);
    u32 bL = bH + PLB;

    u32 bh[2][4], bl[2][4], am[4][4];
    ldsm4(bh[0], bH); ldsm4(bh[1], bH + 1024);
    ldsm4(bl[0], bL); ldsm4(bl[1], bL + 1024);
#pragma unroll
    for (int mf = 0; mf < 4; mf++) ldsm4(am[mf], aH + mf * 1024);
#pragma unroll
    for (int mf = 0; mf < 4; mf++)
#pragma unroll
        for (int nf = 0; nf < 4; nf++) {
            const u32* b = &bh[nf >> 1][(nf & 1) * 2];
            mma_bf16(acc[mf][nf], am[mf][0], am[mf][1], am[mf][2], am[mf][3], b[0], b[1]);
        }
#pragma unroll
    for (int mf = 0; mf < 4; mf++)
#pragma unroll
        for (int nf = 0; nf < 4; nf++) {
            const u32* b = &bl[nf >> 1][(nf & 1) * 2];
            mma_bf16(acc[mf][nf], am[mf][0], am[mf][1], am[mf][2], am[mf][3], b[0], b[1]);
        }
#pragma unroll
    for (int mf = 0; mf < 4; mf++) ldsm4(am[mf], aL + mf * 1024);
#pragma unroll
    for (int mf = 0; mf < 4; mf++)
#pragma unroll
        for (int nf = 0; nf < 4; nf++) {
            const u32* b = &bh[nf >> 1][(nf & 1) * 2];
            mma_bf16(acc[mf][nf], am[mf][0], am[mf][1], am[mf][2], am[mf][3], b[0], b[1]);
        }
}

// ---------------- the one NT GEMM kernel ----------------
enum { M_XA = 1, M_MOE = 2, M_SCORES = 4, M_CTX = 5, M_QKV = 6 };

typedef const __nv_bfloat16 cbf;

template <int MODE>
__global__ void __launch_bounds__(256) tc_gemm(
    cbf* Ah_, cbf* Al_, cbf* Bh_, cbf* Bl_,
    float* __restrict__ Cf, u32* __restrict__ Ch, u32* __restrict__ Cl,
    const float* __restrict__ Lab, const float* __restrict__ Lbb,
    const int* __restrict__ glist, const int* __restrict__ gcnt,
    const float* __restrict__ gw,
    const float* __restrict__ Lb2, const float* __restrict__ Lb3) {
    constexpr bool GATHER = (MODE == M_MOE);
    constexpr bool QKV = (MODE == M_QKV);
    constexpr bool LORA = (MODE == M_MOE || MODE == M_QKV);
    constexpr bool USETOK = (GATHER || QKV);
    extern __shared__ __align__(16) unsigned char dsm[];
    __shared__ int esm[128];
    __shared__ int tok[128];
    __shared__ float s_row[128];

    int tid = threadIdx.x;
    int m0 = blockIdx.y * 128, n0 = blockIdx.x * 128, z = blockIdx.z;

    cbf *pAh, *pAl, *pBh, *pBl;
    const float* La = nullptr;
    const float* Lb = nullptr;
    long lda, ldb, ldc = 0;
    int K, ldla = 0;
    size_t coff = 0;

    if constexpr (MODE == M_XA) {
        pAh = Ah_ + (size_t)m0 * H_; pAl = Al_ + (size_t)m0 * H_;
        pBh = Bh_; pBl = Bl_;
        coff = (size_t)m0 * 128;
        lda = ldb = H_; ldc = 128; K = H_;
    } else if constexpr (MODE == M_MOE) {
        pAh = Ah_; pAl = Al_;
        pBh = Bh_ + (size_t)z * H_ * H_ + (size_t)n0 * H_;
        pBl = Bl_ + (size_t)z * H_ * H_ + (size_t)n0 * H_;
        lda = ldb = H_; K = H_;
        La = Lab + z * R_; ldla = 128;
        Lb = Lbb + (size_t)z * H_ * R_ + (size_t)n0 * R_;
    } else if constexpr (MODE == M_QKV) {
        pAh = (cbf*)g_xs_h; pAl = (cbf*)g_xs_l;
        size_t bo = (size_t)n0 * H_;
        if (z == 0)      { pBh = (cbf*)g_wqs_h + bo; pBl = (cbf*)g_wqs_l + bo; }
        else if (z == 1) { pBh = (cbf*)g_wks_h + bo; pBl = (cbf*)g_wks_l + bo; }
        else {
            size_t eo = (size_t)(z - 2) * H_ * H_;
            pBh = (cbf*)g_vbs_h + eo + bo; pBl = (cbf*)g_vbs_l + eo + bo;
        }
        lda = ldb = H_; K = H_; ldla = 128;
        La = g_xacat + (z == 0 ? 0 : (z == 1 ? 16 : 32 + (z - 2) * R_));
        Lb = (z == 0 ? Lbb : (z == 1 ? Lb2 : Lb3 + (size_t)(z - 2) * H_ * R_)) + (size_t)n0 * R_;
    } else if constexpr (MODE == M_SCORES) {
        int b = z >> 4, h = z & 15;
        size_t ao = ((size_t)b * S_ + m0) * H_ + h * DH_;
        size_t bo = ((size_t)b * S_ + n0) * H_ + h * DH_;
        pAh = Ah_ + ao; pAl = Al_ + ao;
        pBh = Bh_ + bo; pBl = Bl_ + bo;
        coff = (size_t)z * S_ * S_ + (size_t)m0 * S_ + n0;
        lda = ldb = H_; ldc = S_; K = DH_;
    } else {  // M_CTX
        size_t ao = (size_t)z * S_ * S_ + (size_t)m0 * S_;
        size_t bo = (size_t)z * DH_ * S_;
        pAh = Ah_ + ao; pAl = Al_ + ao;
        pBh = Bh_ + bo; pBl = Bl_ + bo;
        int b = z >> 4, h = z & 15;
        coff = ((size_t)b * S_ + m0) * H_ + h * DH_;
        lda = S_; ldb = S_; ldc = H_; K = S_;
    }

    if constexpr (MODE == M_QKV) {
        if (z >= 2 && m0 >= gcnt[z - 2]) return;
        if (tid < 128) {
            if (z < 2) { tok[tid] = m0 + tid; esm[tid] = 0; }
            else {
                int count = gcnt[z - 2];
                int idx = m0 + tid;
                int en = (idx < count) ? glist[(z - 2) * T_ + idx] : -1;
                esm[tid] = en;
                tok[tid] = (en >= 0) ? (en >> 1) : 0;
            }
        }
        __syncthreads();
    } else if constexpr (GATHER) {
        int count = gcnt[z];
        if (m0 >= count) return;
        if (tid < 128) {
            int idx = m0 + tid;
            int en = (idx < count) ? glist[z * T_ + idx] : -1;
            esm[tid] = en;
            tok[tid] = (en >= 0) ? (en >> 1) : 0;
        }
        __syncthreads();
    }
    if constexpr (MODE == M_SCORES) {
        // precomputed additive mask term for this CTA's 128 kv cols
        if (tid < 128) s_row[tid] = (1.0f - gw[(size_t)(z >> 4) * S_ + n0 + tid]) * (-10000.0f);
    }
    if constexpr (MODE == M_CTX) {
        if (tid < 128) s_row[tid] = 1.0f / g_L[(size_t)z * S_ + m0 + tid];
    }

    int wid = tid >> 5, lane = tid & 31;
    int wm = wid & 1, wn = wid >> 1, g = lane >> 2, tig = lane & 3;
    u32 smb = s2u(dsm);

    // per-thread loader pointers: rows cr and cr+64, seg = tid&3
    int cr = tid >> 2, seg = tid & 3;
    int ra0 = cr, ra1 = cr + 64;
    long ga0 = USETOK ? (long)tok[ra0] : ra0;
    long ga1 = USETOK ? (long)tok[ra1] : ra1;
    cbf* sAh0 = pAh + ga0 * lda + seg * 8;
    cbf* sAh1 = pAh + ga1 * lda + seg * 8;
    cbf* sAl0 = pAl + ga0 * lda + seg * 8;
    cbf* sAl1 = pAl + ga1 * lda + seg * 8;
    cbf* sBh0 = pBh + (long)ra0 * ldb + seg * 8;
    cbf* sBh1 = pBh + (long)ra1 * ldb + seg * 8;
    cbf* sBl0 = pBl + (long)ra0 * ldb + seg * 8;
    cbf* sBl1 = pBl + (long)ra1 * ldb + seg * 8;
    u32 d0 = swb(ra0, seg), d1 = swb(ra1, seg);

#define LOAD_STAGE(s, ktE) do { u32 st_ = smb + (s) * STG_B; int k_ = (ktE); \
    cpa16(st_ + d0, sAh0 + k_);            cpa16(st_ + d1, sAh1 + k_); \
    cpa16(st_ + PLB + d0, sAl0 + k_);      cpa16(st_ + PLB + d1, sAl1 + k_); \
    cpa16(st_ + 2 * PLB + d0, sBh0 + k_);  cpa16(st_ + 2 * PLB + d1, sBh1 + k_); \
    cpa16(st_ + 3 * PLB + d0, sBl0 + k_);  cpa16(st_ + 3 * PLB + d1, sBl1 + k_); } while (0)

    float acc[4][4][4];
#pragma unroll
    for (int a = 0; a < 4; a++)
#pragma unroll
        for (int b = 0; b < 4; b++)
#pragma unroll
            for (int c = 0; c < 4; c++) acc[a][b][c] = 0.f;

    int nk = K / 32;
    LOAD_STAGE(0, 0);  CPA_COMMIT();
    LOAD_STAGE(1, 32); CPA_COMMIT();

    for (int it = 0; it < nk; it++) {
        CPA_WAIT1();
        __syncthreads();
        // prefetch FIRST (safe: sync(it) implies compute(it-1) done), then compute
        if (it + 2 < nk) LOAD_STAGE((it + 2) % NSTG, (it + 2) * 32);
        CPA_COMMIT();
        u32 stg = smb + (it % NSTG) * STG_B;
        compute_k16(stg, 0, wm, wn, lane, acc);
        compute_k16(stg, 1, wm, wn, lane, acc);
    }
    CPA_WAIT0();
    __syncthreads();

    if constexpr (LORA) {
        // one extra k16: A = SCALING*La (fp32, rows via tok), B = Lb (fp32); segs 0..1
#pragma unroll
        for (int i = 0; i < 2; i++) {
            int f = tid + i * 256;
            int row = f >> 2, kc = (f & 3) * 4;
            size_t ro = (size_t)tok[row] * ldla;
            float4 v = *(const float4*)(La + ro + kc);
            v.x *= SCALING_; v.y *= SCALING_; v.z *= SCALING_; v.w *= SCALING_;
            u32 h0, h1, l0, l1;
            split4(v, h0, h1, l0, l1);
            u32 off = smb + swb(row, kc >> 3) + (kc & 7) * 2;
            asm volatile("st.shared.v2.u32 [%0], {%1,%2};" :: "r"(off), "r"(h0), "r"(h1));
            asm volatile("st.shared.v2.u32 [%0], {%1,%2};" :: "r"(off + PLB), "r"(l0), "r"(l1));
            float4 u = *(const float4*)(Lb + (size_t)row * R_ + kc);
            split4(u, h0, h1, l0, l1);
            asm volatile("st.shared.v2.u32 [%0], {%1,%2};" :: "r"(off + 2 * PLB), "r"(h0), "r"(h1));
            asm volatile("st.shared.v2.u32 [%0], {%1,%2};" :: "r"(off + 3 * PLB), "r"(l0), "r"(l1));
        }
        __syncthreads();
        compute_k16(smb, 0, wm, wn, lane, acc);
    }

    // ---------------- epilogues ----------------
    if constexpr (MODE == M_QKV) {
        if (z < 2) {
            u32* ch = (z == 0) ? g_qs_h : g_ks_h;
            u32* cl = (z == 0) ? g_qs_l : g_ks_l;
            size_t co = (size_t)m0 * H_ + n0;
#pragma unroll
            for (int mf = 0; mf < 4; mf++) {
#pragma unroll
                for (int half = 0; half < 2; half++) {
                    int m = wm * 64 + mf * 16 + g + half * 8;
#pragma unroll
                    for (int nf = 0; nf < 4; nf++) {
                        int n = wn * 32 + nf * 8 + tig * 2;
                        u32 h, l;
                        split2(acc[mf][nf][half * 2 + 0], acc[mf][nf][half * 2 + 1], h, l);
                        size_t ix = (co + (size_t)m * H_ + n) >> 1;
                        ch[ix] = h;
                        cl[ix] = l;
                    }
                }
            }
        } else {
            // V MoE: UNTRANSPOSED coalesced atomic accumulate into g_vt[t][n]
#pragma unroll
            for (int mf = 0; mf < 4; mf++) {
#pragma unroll
                for (int half = 0; half < 2; half++) {
                    int lr = wm * 64 + mf * 16 + g + half * 8;
                    int en = esm[lr];
                    if (en < 0) continue;
                    float w = gw[en];
                    int t = en >> 1;
                    float* p = g_vt + (size_t)t * H_ + n0;
#pragma unroll
                    for (int nf = 0; nf < 4; nf++) {
                        int n = wn * 32 + nf * 8 + tig * 2;
                        atomicAdd(p + n, w * acc[mf][nf][half * 2 + 0]);
                        atomicAdd(p + n + 1, w * acc[mf][nf][half * 2 + 1]);
                    }
                }
            }
        }
    } else if constexpr (GATHER) {
#pragma unroll
        for (int mf = 0; mf < 4; mf++) {
#pragma unroll
            for (int half = 0; half < 2; half++) {
                int lr = wm * 64 + mf * 16 + g + half * 8;
                int en = esm[lr];
                if (en < 0) continue;
                float w = gw[en];
                int t = en >> 1;
#pragma unroll
                for (int nf = 0; nf < 4; nf++) {
                    int n = n0 + wn * 32 + nf * 8 + tig * 2;
                    float* p = Cf + (size_t)t * H_ + n;
                    atomicAdd(p, w * acc[mf][nf][half * 2 + 0]);
                    atomicAdd(p + 1, w * acc[mf][nf][half * 2 + 1]);
                }
            }
        }
    } else if constexpr (MODE == M_SCORES) {
        // exp epilogue: write unnormalized exp(P) planes + atomic row sums
#pragma unroll
        for (int mf = 0; mf < 4; mf++) {
#pragma unroll
            for (int half = 0; half < 2; half++) {
                int r = wm * 64 + mf * 16 + g + half * 8;
                float rs = 0.f;
#pragma unroll
                for (int nf = 0; nf < 4; nf++) {
                    int cn = wn * 32 + nf * 8 + tig * 2;
                    float e0 = __expf(acc[mf][nf][half * 2 + 0] * INV_SQRT_DH + s_row[cn]);
                    float e1 = __expf(acc[mf][nf][half * 2 + 1] * INV_SQRT_DH + s_row[cn + 1]);
                    rs += e0 + e1;
                    u32 h, l;
                    split2(e0, e1, h, l);
                    size_t ix = (coff + (size_t)r * S_ + cn) >> 1;
                    g_Ps_h[ix] = h;
                    g_Ps_l[ix] = l;
                }
                rs += __shfl_xor_sync(0xffffffffu, rs, 1);
                rs += __shfl_xor_sync(0xffffffffu, rs, 2);
                if (tig == 0) atomicAdd(&g_L[(size_t)z * S_ + m0 + r], rs);
            }
        }
    } else if constexpr (MODE == M_CTX) {
#pragma unroll
        for (int mf = 0; mf < 4; mf++) {
#pragma unroll
            for (int half = 0; half < 2; half++) {
                int m = wm * 64 + mf * 16 + g + half * 8;
                float iv = s_row[m];
#pragma unroll
                for (int nf = 0; nf < 4; nf++) {
                    int n = wn * 32 + nf * 8 + tig * 2;
                    u32 h, l;
                    split2(acc[mf][nf][half * 2 + 0] * iv, acc[mf][nf][half * 2 + 1] * iv, h, l);
                    size_t ix = (coff + (size_t)m * ldc + n) >> 1;
                    Ch[ix] = h;
                    Cl[ix] = l;
                }
            }
        }
    } else {  // M_XA: fp32 out
        float* C = Cf + coff;
#pragma unroll
        for (int mf = 0; mf < 4; mf++) {
#pragma unroll
            for (int half = 0; half < 2; half++) {
                int m = wm * 64 + mf * 16 + g + half * 8;
#pragma unroll
                for (int nf = 0; nf < 4; nf++) {
                    int n = wn * 32 + nf * 8 + tig * 2;
                    float2 v = {acc[mf][nf][half * 2 + 0], acc[mf][nf][half * 2 + 1]};
                    *(float2*)(C + (size_t)m * ldc + n) = v;
                }
            }
        }
    }
#undef LOAD_STAGE
}

// ---------------- transpose + split: g_vt [b][s][n] -> vts planes [b*H+n][S] ----------------
__global__ void tsplit_kernel() {
    __shared__ float tile[32][33];
    int bx = blockIdx.x;          // H / 32 tiles (n)
    int by = blockIdx.y;          // S / 32 tiles (s)
    int bz = blockIdx.z;          // batch
    int tx = threadIdx.x & 31, ty = threadIdx.x >> 5;   // 256 threads: 32 x 8
    // load: rows = s, cols = n (coalesced on n)
#pragma unroll
    for (int r = 0; r < 32; r += 8) {
        tile[r + ty][tx] = g_vt[((size_t)(bz * S_ + by * 32 + r + ty)) * H_ + bx * 32 + tx];
    }
    __syncthreads();
    // store transposed: row = n, packed pairs along s (coalesced)
#pragma unroll
    for (int r = 0; r < 32; r += 8) {
        int n = r + ty;
        if (tx < 16) {
            float a = tile[2 * tx][n], b = tile[2 * tx + 1][n];
            u32 h, l;
            split2(a, b, h, l);
            size_t ix = (((size_t)(bz * H_ + bx * 32 + n)) * S_ + by * 32) / 2 + tx;
            g_vts_h[ix] = h;
            g_vts_l[ix] = l;
        }
    }
}

// ---------------- split fp32 -> bf16 hi/lo planes ----------------
__global__ void split_kernel(const float4* __restrict__ src, u32* __restrict__ hi,
                             u32* __restrict__ lo, int n4) {
    for (int i = blockIdx.x * blockDim.x + threadIdx.x; i < n4; i += gridDim.x * blockDim.x) {
        float4 v = src[i];
        u32 h0, h1, l0, l1;
        split4(v, h0, h1, l0, l1);
        *(uint2*)&hi[(size_t)i * 2] = make_uint2(h0, h1);
        *(uint2*)&lo[(size_t)i * 2] = make_uint2(l0, l1);
    }
}

// ---------------- init counts ----------------
__global__ void init_counts_kernel() {
    if (threadIdx.x < E_) {
        g_cnt_v[threadIdx.x] = 0;
        g_cnt_o[threadIdx.x] = 0;
    }
}

// ---------------- routing ----------------
__global__ void routing_kernel(const float* __restrict__ x,
                               const float* __restrict__ gv,
                               const float* __restrict__ go) {
    int t = blockIdx.x;
    const float* xt = x + (size_t)t * H_;
    float pv[E_], po[E_];
#pragma unroll
    for (int e = 0; e < E_; e++) { pv[e] = 0.f; po[e] = 0.f; }
    for (int k = threadIdx.x; k < H_; k += 128) {
        float xv = xt[k];
#pragma unroll
        for (int e = 0; e < E_; e++) {
            pv[e] += xv * gv[e * H_ + k];
            po[e] += xv * go[e * H_ + k];
        }
    }
    __shared__ float red[2 * E_][128];
#pragma unroll
    for (int e = 0; e < E_; e++) {
        red[e][threadIdx.x] = pv[e];
        red[E_ + e][threadIdx.x] = po[e];
    }
    __syncthreads();
    if (threadIdx.x < 2 * E_) {
        float s = 0.f;
        for (int i = 0; i < 128; i++) s += red[threadIdx.x][i];
        red[threadIdx.x][0] = s;
    }
    __syncthreads();
    if (threadIdx.x < 2) {
        bool isO = (threadIdx.x == 1);
        float sc[E_];
#pragma unroll
        for (int e = 0; e < E_; e++) {
            float d = red[(isO ? E_ : 0) + e][0];
            sc[e] = 1.f / (1.f + expf(-d));
        }
        int e0 = 0;
        for (int e = 1; e < E_; e++) if (sc[e] > sc[e0]) e0 = e;
        int e1 = -1;
        for (int e = 0; e < E_; e++) {
            if (e == e0) continue;
            if (e1 < 0 || sc[e] > sc[e1]) e1 = e;
        }
        float t1 = expf(sc[e1] - sc[e0]);
        float w0 = 1.f / (1.f + t1);
        float w1 = t1 / (1.f + t1);
        if (!isO) {
            g_wslot_v[t * 2 + 0] = w0;
            g_wslot_v[t * 2 + 1] = w1;
            int p0 = atomicAdd(&g_cnt_v[e0], 1); g_list_v[e0 * T_ + p0] = t * 2 + 0;
            int p1 = atomicAdd(&g_cnt_v[e1], 1); g_list_v[e1 * T_ + p1] = t * 2 + 1;
        } else {
            g_wslot_o[t * 2 + 0] = w0;
            g_wslot_o[t * 2 + 1] = w1;
            int p0 = atomicAdd(&g_cnt_o[e0], 1); g_list_o[e0 * T_ + p0] = t * 2 + 0;
            int p1 = atomicAdd(&g_cnt_o[e1], 1); g_list_o[e1 * T_ + p1] = t * 2 + 1;
        }
    }
}

// ---------------- launcher ----------------
extern "C" void kernel_launch(void* const* d_in, const int* in_sizes, int n_in,
                              void* d_out, int out_size) {
    const float* x      = (const float*)d_in[0];
    const float* amask  = (const float*)d_in[1];
    const float* wq     = (const float*)d_in[2];
    const float* wk     = (const float*)d_in[3];
    const float* q_a    = (const float*)d_in[4];
    const float* q_b    = (const float*)d_in[5];
    const float* k_a    = (const float*)d_in[6];
    const float* k_b    = (const float*)d_in[7];
    const float* gv     = (const float*)d_in[8];
    const float* go     = (const float*)d_in[9];
    const float* v_base = (const float*)d_in[10];
    const float* v_a    = (const float*)d_in[11];
    const float* v_b    = (const float*)d_in[12];
    const float* o_base = (const float*)d_in[13];
    const float* o_a    = (const float*)d_in[14];
    const float* o_b    = (const float*)d_in[15];
    float* out = (float*)d_out;

#define SYM(v, s) void* v; cudaGetSymbolAddress(&v, s)
    SYM(p_vt, g_vt); SYM(p_L, g_L); SYM(p_xacat, g_xacat); SYM(p_xao, g_xao);
    SYM(p_wcat, g_wcat); SYM(p_wcat2, g_wcat2);
    SYM(p_list_v, g_list_v); SYM(p_list_o, g_list_o);
    SYM(p_cnt_v, g_cnt_v); SYM(p_cnt_o, g_cnt_o);
    SYM(p_ws_v, g_wslot_v); SYM(p_ws_o, g_wslot_o);
    SYM(xs_h, g_xs_h); SYM(xs_l, g_xs_l);
    SYM(qs_h, g_qs_h); SYM(qs_l, g_qs_l);
    SYM(ks_h, g_ks_h); SYM(ks_l, g_ks_l);
    SYM(cts_h, g_cts_h); SYM(cts_l, g_cts_l);
    SYM(vts_h, g_vts_h); SYM(vts_l, g_vts_l);
    SYM(Ps_h, g_Ps_h); SYM(Ps_l, g_Ps_l);
    SYM(wqs_h, g_wqs_h); SYM(wqs_l, g_wqs_l);
    SYM(wks_h, g_wks_h); SYM(wks_l, g_wks_l);
    SYM(vbs_h, g_vbs_h); SYM(vbs_l, g_vbs_l);
    SYM(obs_h, g_obs_h); SYM(obs_l, g_obs_l);
    SYM(wcs_h, g_wcs_h); SYM(wcs_l, g_wcs_l);
    SYM(wcs2_h, g_wcs2_h); SYM(wcs2_l, g_wcs2_l);
#undef SYM

    cudaFuncSetAttribute(tc_gemm<M_XA>,     cudaFuncAttributeMaxDynamicSharedMemorySize, SMEM_SZ);
    cudaFuncSetAttribute(tc_gemm<M_MOE>,    cudaFuncAttributeMaxDynamicSharedMemorySize, SMEM_SZ);
    cudaFuncSetAttribute(tc_gemm<M_QKV>,    cudaFuncAttributeMaxDynamicSharedMemorySize, SMEM_SZ);
    cudaFuncSetAttribute(tc_gemm<M_SCORES>, cudaFuncAttributeMaxDynamicSharedMemorySize, SMEM_SZ);
    cudaFuncSetAttribute(tc_gemm<M_CTX>,    cudaFuncAttributeMaxDynamicSharedMemorySize, SMEM_SZ);

    // LoRA-A weight concats (fp32)
    cudaMemcpyAsync((float*)p_wcat,           q_a, sizeof(float) * R_ * H_,      cudaMemcpyDeviceToDevice);
    cudaMemcpyAsync((float*)p_wcat + 16 * H_, k_a, sizeof(float) * R_ * H_,      cudaMemcpyDeviceToDevice);
    cudaMemcpyAsync((float*)p_wcat + 32 * H_, v_a, sizeof(float) * E_ * R_ * H_, cudaMemcpyDeviceToDevice);
    cudaMemcpyAsync((float*)p_wcat2,          o_a, sizeof(float) * E_ * R_ * H_, cudaMemcpyDeviceToDevice);

    cudaMemsetAsync(p_vt, 0, sizeof(float) * (size_t)T_ * H_);
    cudaMemsetAsync(p_L, 0, sizeof(float) * (size_t)B_ * NH_ * S_);
    cudaMemsetAsync(out, 0, sizeof(float) * (size_t)T_ * H_);
    init_counts_kernel<<<1, 32>>>();
    routing_kernel<<<T_, 128>>>(x, gv, go);

    // splits: inputs + weights
    split_kernel<<<1024, 256>>>((const float4*)x,      (u32*)xs_h,  (u32*)xs_l,  T_ * H_ / 4);
    split_kernel<<<1024, 256>>>((const float4*)wq,     (u32*)wqs_h, (u32*)wqs_l, H_ * H_ / 4);
    split_kernel<<<1024, 256>>>((const float4*)wk,     (u32*)wks_h, (u32*)wks_l, H_ * H_ / 4);
    split_kernel<<<2048, 256>>>((const float4*)v_base, (u32*)vbs_h, (u32*)vbs_l, E_ * H_ * H_ / 4);
    split_kernel<<<2048, 256>>>((const float4*)o_base, (u32*)obs_h, (u32*)obs_l, E_ * H_ * H_ / 4);
    split_kernel<<<256, 256>>>((const float4*)p_wcat,  (u32*)wcs_h, (u32*)wcs_l, 128 * H_ / 4);
    split_kernel<<<256, 256>>>((const float4*)p_wcat2, (u32*)wcs2_h, (u32*)wcs2_l, 128 * H_ / 4);

    // XA: xacat = x @ wcat^T (fp32 out)
    tc_gemm<M_XA><<<dim3(1, T_ / 128), 256, SMEM_SZ>>>(
        (cbf*)xs_h, (cbf*)xs_l, (cbf*)wcs_h, (cbf*)wcs_l,
        (float*)p_xacat, nullptr, nullptr, nullptr, nullptr, nullptr, nullptr, nullptr,
        nullptr, nullptr);

    // fused Q-proj (z=0), K-proj (z=1), V-MoE (z=2..7, untransposed atomic V)
    tc_gemm<M_QKV><<<dim3(H_ / 128, T_ / 128, 2 + E_), 256, SMEM_SZ>>>(
        nullptr, nullptr, nullptr, nullptr,
        nullptr, nullptr, nullptr,
        nullptr, q_b,
        (const int*)p_list_v, (const int*)p_cnt_v, (const float*)p_ws_v,
        k_b, v_b);

    // transpose + split V -> vts planes
    tsplit_kernel<<<dim3(H_ / 32, S_ / 32, B_), 256>>>();

    // attention: scores with fused exp + row-sum epilogue, then ctx with 1/L epilogue
    tc_gemm<M_SCORES><<<dim3(S_ / 128, S_ / 128, B_ * NH_), 256, SMEM_SZ>>>(
        (cbf*)qs_h, (cbf*)qs_l, (cbf*)ks_h, (cbf*)ks_l,
        nullptr, nullptr, nullptr, nullptr, nullptr, nullptr, nullptr, amask,
        nullptr, nullptr);
    tc_gemm<M_CTX><<<dim3(1, S_ / 128, B_ * NH_), 256, SMEM_SZ>>>(
        (cbf*)Ps_h, (cbf*)Ps_l, (cbf*)vts_h, (cbf*)vts_l,
        nullptr, (u32*)cts_h, (u32*)cts_l, nullptr, nullptr, nullptr, nullptr, nullptr,
        nullptr, nullptr);

    // O path
    tc_gemm<M_XA><<<dim3(1, T_ / 128), 256, SMEM_SZ>>>(
        (cbf*)cts_h, (cbf*)cts_l, (cbf*)wcs2_h, (cbf*)wcs2_l,
        (float*)p_xao, nullptr, nullptr, nullptr, nullptr, nullptr, nullptr, nullptr,
        nullptr, nullptr);
    tc_gemm<M_MOE><<<dim3(H_ / 128, T_ / 128, E_), 256, SMEM_SZ>>>(
        (cbf*)cts_h, (cbf*)cts_l, (cbf*)obs_h, (cbf*)obs_l,
        out, nullptr, nullptr, (const float*)p_xao, o_b,
        (const int*)p_list_o, (const int*)p_cnt_o, (const float*)p_ws_o,
        nullptr, nullptr);
}

// round 13
// speedup vs baseline: 1.1000x; 1.0841x over previous
#include <cuda_runtime.h>
#include <cuda_bf16.h>
#include <math.h>

typedef unsigned int u32;
typedef unsigned long long u64;

// ---------------- problem constants ----------------
#define B_   2
#define S_   2048
#define H_   2048
#define NH_  16
#define DH_  128
#define E_   6
#define R_   16
#define T_   (B_ * S_)            // 4096 tokens
#define SCALING_ 8.0f
#define INV_SQRT_DH 0.08838834764831845f

// tile: 128 rows x 32 bf16 = 64B/row, XOR-swizzled. 8KB per plane.
#define PLB 8192
#define STG_B (4 * PLB)           // Ahi, Alo, Bhi, Blo = 32KB
#define NSTG 3
#define SMEM_SZ (NSTG * STG_B)    // 96KB

// ---------------- scratch: fp32 ----------------
__device__ float g_vt[T_ * H_];        // V untransposed [t][n] (atomic accum)
__device__ float g_L[B_ * NH_ * S_];   // unnormalized softmax row sums
__device__ float g_xacat[T_ * 128];
__device__ float g_xao[T_ * 128];
__device__ float g_wcat[128 * H_];
__device__ float g_wcat2[128 * H_];
__device__ int   g_list_v[E_ * T_];
__device__ int   g_list_o[E_ * T_];
__device__ int   g_cnt_v[E_];
__device__ int   g_cnt_o[E_];
__device__ float g_wslot_v[T_ * 2];
__device__ float g_wslot_o[T_ * 2];

// ---------------- scratch: bf16 hi/lo planes (u32 = 2 bf16) ----------------
#define PT (T_ * H_ / 2)
#define PW (H_ * H_ / 2)
#define PE (E_ * H_ * H_ / 2)
#define PC (128 * H_ / 2)
__device__ u32 g_xs_h[PT],  g_xs_l[PT];
__device__ u32 g_qs_h[PT],  g_qs_l[PT];
__device__ u32 g_ks_h[PT],  g_ks_l[PT];
__device__ u32 g_cts_h[PT], g_cts_l[PT];
__device__ u32 g_vts_h[PT], g_vts_l[PT];   // V transposed planes [b*H+n][S]
__device__ u32 g_Ps_h[(size_t)B_ * NH_ * S_ * S_ / 2];
__device__ u32 g_Ps_l[(size_t)B_ * NH_ * S_ * S_ / 2];
__device__ u32 g_wqs_h[PW], g_wqs_l[PW];
__device__ u32 g_wks_h[PW], g_wks_l[PW];
__device__ u32 g_vbs_h[PE], g_vbs_l[PE];
__device__ u32 g_obs_h[PE], g_obs_l[PE];
__device__ u32 g_wcs_h[PC], g_wcs_l[PC];
__device__ u32 g_wcs2_h[PC], g_wcs2_l[PC];

// ---------------- helpers ----------------
__device__ __forceinline__ u32 s2u(const void* p) {
    u32 a;
    asm("{ .reg .u64 t; cvta.to.shared.u64 t, %1; cvt.u32.u64 %0, t; }" : "=r"(a) : "l"(p));
    return a;
}
__device__ __forceinline__ u32 pack_bf2(float a, float b) {
    __nv_bfloat162 t = __floats2bfloat162_rn(a, b);
    return *reinterpret_cast<u32*>(&t);
}
__device__ __forceinline__ void split4(float4 v, u32& h0, u32& h1, u32& l0, u32& l1) {
    __nv_bfloat162 p0 = __floats2bfloat162_rn(v.x, v.y);
    __nv_bfloat162 p1 = __floats2bfloat162_rn(v.z, v.w);
    h0 = *reinterpret_cast<u32*>(&p0);
    h1 = *reinterpret_cast<u32*>(&p1);
    l0 = pack_bf2(v.x - __low2float(p0), v.y - __high2float(p0));
    l1 = pack_bf2(v.z - __low2float(p1), v.w - __high2float(p1));
}
__device__ __forceinline__ void split2(float a, float b, u32& h, u32& l) {
    __nv_bfloat162 p = __floats2bfloat162_rn(a, b);
    h = *reinterpret_cast<u32*>(&p);
    l = pack_bf2(a - __low2float(p), b - __high2float(p));
}
__device__ __forceinline__ void mma_bf16(float* c, u32 a0, u32 a1, u32 a2, u32 a3, u32 b0, u32 b1) {
    asm volatile(
        "mma.sync.aligned.m16n8k16.row.col.f32.bf16.bf16.f32 "
        "{%0,%1,%2,%3}, {%4,%5,%6,%7}, {%8,%9}, {%0,%1,%2,%3};"
        : "+f"(c[0]), "+f"(c[1]), "+f"(c[2]), "+f"(c[3])
        : "r"(a0), "r"(a1), "r"(a2), "r"(a3), "r"(b0), "r"(b1));
}
__device__ __forceinline__ void ldsm4(u32* r, u32 a) {
    asm volatile("ldmatrix.sync.aligned.m8n8.x4.shared.b16 {%0,%1,%2,%3}, [%4];"
        : "=r"(r[0]), "=r"(r[1]), "=r"(r[2]), "=r"(r[3]) : "r"(a));
}
__device__ __forceinline__ void cpa16(u32 dst, const void* src) {
    asm volatile("cp.async.ca.shared.global [%0], [%1], 16;" :: "r"(dst), "l"(src));
}
#define CPA_COMMIT() asm volatile("cp.async.commit_group;" ::: "memory")
#define CPA_WAIT1()  asm volatile("cp.async.wait_group 1;" ::: "memory")
#define CPA_WAIT0()  asm volatile("cp.async.wait_group 0;" ::: "memory")
// XOR swizzle: row 64B, seg = 16B chunk idx (0..3)
__device__ __forceinline__ u32 swb(int row, int seg) {
    return (u32)(row * 64 + ((seg ^ ((row >> 1) & 3)) * 16));
}

// one k16 MMA step over 128x128 tile (3-term bf16 split), stage base = stg
__device__ __forceinline__ void compute_k16(u32 stg, int ks, int wm, int wn, int lane,
                                            float (&acc)[4][4][4]) {
    int j = lane >> 3, r7 = lane & 7;
    int rowA = wm * 64 + (j & 1) * 8 + r7;
    int segA = ks * 2 + (j >> 1);
    u32 aH = stg + swb(rowA, segA);
    u32 aL = aH + PLB;
    int rowB = wn * 32 + (j >> 1) * 8 + r7;
    int segB = ks * 2 + (j & 1);
    u32 bH = stg + 2 * PLB + swb(rowB, segB);
    u32 bL = bH + PLB;

    u32 bh[2][4], bl[2][4], am[4][4];
    ldsm4(bh[0], bH); ldsm4(bh[1], bH + 1024);
    ldsm4(bl[0], bL); ldsm4(bl[1], bL + 1024);
#pragma unroll
    for (int mf = 0; mf < 4; mf++) ldsm4(am[mf], aH + mf * 1024);
#pragma unroll
    for (int mf = 0; mf < 4; mf++)
#pragma unroll
        for (int nf = 0; nf < 4; nf++) {
            const u32* b = &bh[nf >> 1][(nf & 1) * 2];
            mma_bf16(acc[mf][nf], am[mf][0], am[mf][1], am[mf][2], am[mf][3], b[0], b[1]);
        }
#pragma unroll
    for (int mf = 0; mf < 4; mf++)
#pragma unroll
        for (int nf = 0; nf < 4; nf++) {
            const u32* b = &bl[nf >> 1][(nf & 1) * 2];
            mma_bf16(acc[mf][nf], am[mf][0], am[mf][1], am[mf][2], am[mf][3], b[0], b[1]);
        }
#pragma unroll
    for (int mf = 0; mf < 4; mf++) ldsm4(am[mf], aL + mf * 1024);
#pragma unroll
    for (int mf = 0; mf < 4; mf++)
#pragma unroll
        for (int nf = 0; nf < 4; nf++) {
            const u32* b = &bh[nf >> 1][(nf & 1) * 2];
            mma_bf16(acc[mf][nf], am[mf][0], am[mf][1], am[mf][2], am[mf][3], b[0], b[1]);
        }
}

// ---------------- the one NT GEMM kernel ----------------
enum { M_XA = 1, M_MOE = 2, M_SCORES = 4, M_CTX = 5, M_QKV = 6 };

typedef const __nv_bfloat16 cbf;

template <int MODE>
__global__ void __launch_bounds__(256) tc_gemm(
    cbf* Ah_, cbf* Al_, cbf* Bh_, cbf* Bl_,
    float* __restrict__ Cf, u32* __restrict__ Ch, u32* __restrict__ Cl,
    const float* __restrict__ Lab, const float* __restrict__ Lbb,
    const int* __restrict__ glist, const int* __restrict__ gcnt,
    const float* __restrict__ gw,
    const float* __restrict__ Lb2, const float* __restrict__ Lb3) {
    constexpr bool GATHER = (MODE == M_MOE);
    constexpr bool QKV = (MODE == M_QKV);
    constexpr bool LORA = (MODE == M_MOE || MODE == M_QKV);
    constexpr bool USETOK = (GATHER || QKV);
    extern __shared__ __align__(16) unsigned char dsm[];
    __shared__ int esm[128];
    __shared__ int tok[128];
    __shared__ float s_row[128];

    int tid = threadIdx.x;
    int m0 = blockIdx.y * 128, n0 = blockIdx.x * 128, z = blockIdx.z;

    cbf *pAh, *pAl, *pBh, *pBl;
    const float* La = nullptr;
    const float* Lb = nullptr;
    long lda, ldb, ldc = 0;
    int K, ldla = 0;
    size_t coff = 0;

    if constexpr (MODE == M_XA) {
        pAh = Ah_ + (size_t)m0 * H_; pAl = Al_ + (size_t)m0 * H_;
        pBh = Bh_; pBl = Bl_;
        coff = (size_t)m0 * 128;
        lda = ldb = H_; ldc = 128; K = H_;
    } else if constexpr (MODE == M_MOE) {
        pAh = Ah_; pAl = Al_;
        pBh = Bh_ + (size_t)z * H_ * H_ + (size_t)n0 * H_;
        pBl = Bl_ + (size_t)z * H_ * H_ + (size_t)n0 * H_;
        lda = ldb = H_; K = H_;
        La = Lab + z * R_; ldla = 128;
        Lb = Lbb + (size_t)z * H_ * R_ + (size_t)n0 * R_;
    } else if constexpr (MODE == M_QKV) {
        pAh = (cbf*)g_xs_h; pAl = (cbf*)g_xs_l;
        size_t bo = (size_t)n0 * H_;
        if (z == 0)      { pBh = (cbf*)g_wqs_h + bo; pBl = (cbf*)g_wqs_l + bo; }
        else if (z == 1) { pBh = (cbf*)g_wks_h + bo; pBl = (cbf*)g_wks_l + bo; }
        else {
            size_t eo = (size_t)(z - 2) * H_ * H_;
            pBh = (cbf*)g_vbs_h + eo + bo; pBl = (cbf*)g_vbs_l + eo + bo;
        }
        lda = ldb = H_; K = H_; ldla = 128;
        La = g_xacat + (z == 0 ? 0 : (z == 1 ? 16 : 32 + (z - 2) * R_));
        Lb = (z == 0 ? Lbb : (z == 1 ? Lb2 : Lb3 + (size_t)(z - 2) * H_ * R_)) + (size_t)n0 * R_;
    } else if constexpr (MODE == M_SCORES) {
        int b = z >> 4, h = z & 15;
        size_t ao = ((size_t)b * S_ + m0) * H_ + h * DH_;
        size_t bo = ((size_t)b * S_ + n0) * H_ + h * DH_;
        pAh = Ah_ + ao; pAl = Al_ + ao;
        pBh = Bh_ + bo; pBl = Bl_ + bo;
        coff = (size_t)z * S_ * S_ + (size_t)m0 * S_ + n0;
        lda = ldb = H_; ldc = S_; K = DH_;
    } else {  // M_CTX
        size_t ao = (size_t)z * S_ * S_ + (size_t)m0 * S_;
        size_t bo = (size_t)z * DH_ * S_;
        pAh = Ah_ + ao; pAl = Al_ + ao;
        pBh = Bh_ + bo; pBl = Bl_ + bo;
        int b = z >> 4, h = z & 15;
        coff = ((size_t)b * S_ + m0) * H_ + h * DH_;
        lda = S_; ldb = S_; ldc = H_; K = S_;
    }

    if constexpr (MODE == M_QKV) {
        if (z >= 2 && m0 >= gcnt[z - 2]) return;
        if (tid < 128) {
            if (z < 2) { tok[tid] = m0 + tid; esm[tid] = 0; }
            else {
                int count = gcnt[z - 2];
                int idx = m0 + tid;
                int en = (idx < count) ? glist[(z - 2) * T_ + idx] : -1;
                esm[tid] = en;
                tok[tid] = (en >= 0) ? (en >> 1) : 0;
            }
        }
        __syncthreads();
    } else if constexpr (GATHER) {
        int count = gcnt[z];
        if (m0 >= count) return;
        if (tid < 128) {
            int idx = m0 + tid;
            int en = (idx < count) ? glist[z * T_ + idx] : -1;
            esm[tid] = en;
            tok[tid] = (en >= 0) ? (en >> 1) : 0;
        }
        __syncthreads();
    }
    if constexpr (MODE == M_SCORES) {
        // precomputed additive mask term for this CTA's 128 kv cols
        if (tid < 128) s_row[tid] = (1.0f - gw[(size_t)(z >> 4) * S_ + n0 + tid]) * (-10000.0f);
    }
    if constexpr (MODE == M_CTX) {
        if (tid < 128) s_row[tid] = 1.0f / g_L[(size_t)z * S_ + m0 + tid];
    }

    int wid = tid >> 5, lane = tid & 31;
    int wm = wid & 1, wn = wid >> 1, g = lane >> 2, tig = lane & 3;
    u32 smb = s2u(dsm);

    // per-thread loader pointers: rows cr and cr+64, seg = tid&3
    int cr = tid >> 2, seg = tid & 3;
    int ra0 = cr, ra1 = cr + 64;
    long ga0 = USETOK ? (long)tok[ra0] : ra0;
    long ga1 = USETOK ? (long)tok[ra1] : ra1;
    cbf* sAh0 = pAh + ga0 * lda + seg * 8;
    cbf* sAh1 = pAh + ga1 * lda + seg * 8;
    cbf* sAl0 = pAl + ga0 * lda + seg * 8;
    cbf* sAl1 = pAl + ga1 * lda + seg * 8;
    cbf* sBh0 = pBh + (long)ra0 * ldb + seg * 8;
    cbf* sBh1 = pBh + (long)ra1 * ldb + seg * 8;
    cbf* sBl0 = pBl + (long)ra0 * ldb + seg * 8;
    cbf* sBl1 = pBl + (long)ra1 * ldb + seg * 8;
    u32 d0 = swb(ra0, seg), d1 = swb(ra1, seg);

#define LOAD_STAGE(s, ktE) do { u32 st_ = smb + (s) * STG_B; int k_ = (ktE); \
    cpa16(st_ + d0, sAh0 + k_);            cpa16(st_ + d1, sAh1 + k_); \
    cpa16(st_ + PLB + d0, sAl0 + k_);      cpa16(st_ + PLB + d1, sAl1 + k_); \
    cpa16(st_ + 2 * PLB + d0, sBh0 + k_);  cpa16(st_ + 2 * PLB + d1, sBh1 + k_); \
    cpa16(st_ + 3 * PLB + d0, sBl0 + k_);  cpa16(st_ + 3 * PLB + d1, sBl1 + k_); } while (0)

    float acc[4][4][4];
#pragma unroll
    for (int a = 0; a < 4; a++)
#pragma unroll
        for (int b = 0; b < 4; b++)
#pragma unroll
            for (int c = 0; c < 4; c++) acc[a][b][c] = 0.f;

    int nk = K / 32;
    LOAD_STAGE(0, 0);  CPA_COMMIT();
    LOAD_STAGE(1, 32); CPA_COMMIT();

    for (int it = 0; it < nk; it++) {
        CPA_WAIT1();
        __syncthreads();
        // R8 schedule: compute FIRST, then prefetch (MMAs start immediately post-sync)
        u32 stg = smb + (it % NSTG) * STG_B;
        compute_k16(stg, 0, wm, wn, lane, acc);
        compute_k16(stg, 1, wm, wn, lane, acc);
        if (it + 2 < nk) LOAD_STAGE((it + 2) % NSTG, (it + 2) * 32);
        CPA_COMMIT();
    }
    CPA_WAIT0();
    __syncthreads();

    if constexpr (LORA) {
        // one extra k16: A = SCALING*La (fp32, rows via tok), B = Lb (fp32); segs 0..1
#pragma unroll
        for (int i = 0; i < 2; i++) {
            int f = tid + i * 256;
            int row = f >> 2, kc = (f & 3) * 4;
            size_t ro = (size_t)tok[row] * ldla;
            float4 v = *(const float4*)(La + ro + kc);
            v.x *= SCALING_; v.y *= SCALING_; v.z *= SCALING_; v.w *= SCALING_;
            u32 h0, h1, l0, l1;
            split4(v, h0, h1, l0, l1);
            u32 off = smb + swb(row, kc >> 3) + (kc & 7) * 2;
            asm volatile("st.shared.v2.u32 [%0], {%1,%2};" :: "r"(off), "r"(h0), "r"(h1));
            asm volatile("st.shared.v2.u32 [%0], {%1,%2};" :: "r"(off + PLB), "r"(l0), "r"(l1));
            float4 u = *(const float4*)(Lb + (size_t)row * R_ + kc);
            split4(u, h0, h1, l0, l1);
            asm volatile("st.shared.v2.u32 [%0], {%1,%2};" :: "r"(off + 2 * PLB), "r"(h0), "r"(h1));
            asm volatile("st.shared.v2.u32 [%0], {%1,%2};" :: "r"(off + 3 * PLB), "r"(l0), "r"(l1));
        }
        __syncthreads();
        compute_k16(smb, 0, wm, wn, lane, acc);
    }

    // ---------------- epilogues ----------------
    if constexpr (MODE == M_QKV) {
        if (z < 2) {
            u32* ch = (z == 0) ? g_qs_h : g_ks_h;
            u32* cl = (z == 0) ? g_qs_l : g_ks_l;
            size_t co = (size_t)m0 * H_ + n0;
#pragma unroll
            for (int mf = 0; mf < 4; mf++) {
#pragma unroll
                for (int half = 0; half < 2; half++) {
                    int m = wm * 64 + mf * 16 + g + half * 8;
#pragma unroll
                    for (int nf = 0; nf < 4; nf++) {
                        int n = wn * 32 + nf * 8 + tig * 2;
                        u32 h, l;
                        split2(acc[mf][nf][half * 2 + 0], acc[mf][nf][half * 2 + 1], h, l);
                        size_t ix = (co + (size_t)m * H_ + n) >> 1;
                        ch[ix] = h;
                        cl[ix] = l;
                    }
                }
            }
        } else {
            // V MoE: UNTRANSPOSED coalesced atomic accumulate into g_vt[t][n]
#pragma unroll
            for (int mf = 0; mf < 4; mf++) {
#pragma unroll
                for (int half = 0; half < 2; half++) {
                    int lr = wm * 64 + mf * 16 + g + half * 8;
                    int en = esm[lr];
                    if (en < 0) continue;
                    float w = gw[en];
                    int t = en >> 1;
                    float* p = g_vt + (size_t)t * H_ + n0;
#pragma unroll
                    for (int nf = 0; nf < 4; nf++) {
                        int n = wn * 32 + nf * 8 + tig * 2;
                        atomicAdd(p + n, w * acc[mf][nf][half * 2 + 0]);
                        atomicAdd(p + n + 1, w * acc[mf][nf][half * 2 + 1]);
                    }
                }
            }
        }
    } else if constexpr (GATHER) {
#pragma unroll
        for (int mf = 0; mf < 4; mf++) {
#pragma unroll
            for (int half = 0; half < 2; half++) {
                int lr = wm * 64 + mf * 16 + g + half * 8;
                int en = esm[lr];
                if (en < 0) continue;
                float w = gw[en];
                int t = en >> 1;
#pragma unroll
                for (int nf = 0; nf < 4; nf++) {
                    int n = n0 + wn * 32 + nf * 8 + tig * 2;
                    float* p = Cf + (size_t)t * H_ + n;
                    atomicAdd(p, w * acc[mf][nf][half * 2 + 0]);
                    atomicAdd(p + 1, w * acc[mf][nf][half * 2 + 1]);
                }
            }
        }
    } else if constexpr (MODE == M_SCORES) {
        // exp epilogue: write unnormalized exp(P) planes + atomic row sums
#pragma unroll
        for (int mf = 0; mf < 4; mf++) {
#pragma unroll
            for (int half = 0; half < 2; half++) {
                int r = wm * 64 + mf * 16 + g + half * 8;
                float rs = 0.f;
#pragma unroll
                for (int nf = 0; nf < 4; nf++) {
                    int cn = wn * 32 + nf * 8 + tig * 2;
                    float e0 = __expf(acc[mf][nf][half * 2 + 0] * INV_SQRT_DH + s_row[cn]);
                    float e1 = __expf(acc[mf][nf][half * 2 + 1] * INV_SQRT_DH + s_row[cn + 1]);
                    rs += e0 + e1;
                    u32 h, l;
                    split2(e0, e1, h, l);
                    size_t ix = (coff + (size_t)r * S_ + cn) >> 1;
                    g_Ps_h[ix] = h;
                    g_Ps_l[ix] = l;
                }
                rs += __shfl_xor_sync(0xffffffffu, rs, 1);
                rs += __shfl_xor_sync(0xffffffffu, rs, 2);
                if (tig == 0) atomicAdd(&g_L[(size_t)z * S_ + m0 + r], rs);
            }
        }
    } else if constexpr (MODE == M_CTX) {
#pragma unroll
        for (int mf = 0; mf < 4; mf++) {
#pragma unroll
            for (int half = 0; half < 2; half++) {
                int m = wm * 64 + mf * 16 + g + half * 8;
                float iv = s_row[m];
#pragma unroll
                for (int nf = 0; nf < 4; nf++) {
                    int n = wn * 32 + nf * 8 + tig * 2;
                    u32 h, l;
                    split2(acc[mf][nf][half * 2 + 0] * iv, acc[mf][nf][half * 2 + 1] * iv, h, l);
                    size_t ix = (coff + (size_t)m * ldc + n) >> 1;
                    Ch[ix] = h;
                    Cl[ix] = l;
                }
            }
        }
    } else {  // M_XA: fp32 out
        float* C = Cf + coff;
#pragma unroll
        for (int mf = 0; mf < 4; mf++) {
#pragma unroll
            for (int half = 0; half < 2; half++) {
                int m = wm * 64 + mf * 16 + g + half * 8;
#pragma unroll
                for (int nf = 0; nf < 4; nf++) {
                    int n = wn * 32 + nf * 8 + tig * 2;
                    float2 v = {acc[mf][nf][half * 2 + 0], acc[mf][nf][half * 2 + 1]};
                    *(float2*)(C + (size_t)m * ldc + n) = v;
                }
            }
        }
    }
#undef LOAD_STAGE
}

// ---------------- transpose + split: g_vt [b][s][n] -> vts planes [b*H+n][S] ----------------
__global__ void tsplit_kernel() {
    __shared__ float tile[32][33];
    int bx = blockIdx.x;          // H / 32 tiles (n)
    int by = blockIdx.y;          // S / 32 tiles (s)
    int bz = blockIdx.z;          // batch
    int tx = threadIdx.x & 31, ty = threadIdx.x >> 5;   // 256 threads: 32 x 8
    // load: rows = s, cols = n (coalesced on n)
#pragma unroll
    for (int r = 0; r < 32; r += 8) {
        tile[r + ty][tx] = g_vt[((size_t)(bz * S_ + by * 32 + r + ty)) * H_ + bx * 32 + tx];
    }
    __syncthreads();
    // store transposed: row = n, packed pairs along s (coalesced)
#pragma unroll
    for (int r = 0; r < 32; r += 8) {
        int n = r + ty;
        if (tx < 16) {
            float a = tile[2 * tx][n], b = tile[2 * tx + 1][n];
            u32 h, l;
            split2(a, b, h, l);
            size_t ix = (((size_t)(bz * H_ + bx * 32 + n)) * S_ + by * 32) / 2 + tx;
            g_vts_h[ix] = h;
            g_vts_l[ix] = l;
        }
    }
}

// ---------------- split fp32 -> bf16 hi/lo planes ----------------
__global__ void split_kernel(const float4* __restrict__ src, u32* __restrict__ hi,
                             u32* __restrict__ lo, int n4) {
    for (int i = blockIdx.x * blockDim.x + threadIdx.x; i < n4; i += gridDim.x * blockDim.x) {
        float4 v = src[i];
        u32 h0, h1, l0, l1;
        split4(v, h0, h1, l0, l1);
        *(uint2*)&hi[(size_t)i * 2] = make_uint2(h0, h1);
        *(uint2*)&lo[(size_t)i * 2] = make_uint2(l0, l1);
    }
}

// ---------------- init counts ----------------
__global__ void init_counts_kernel() {
    if (threadIdx.x < E_) {
        g_cnt_v[threadIdx.x] = 0;
        g_cnt_o[threadIdx.x] = 0;
    }
}

// ---------------- routing ----------------
__global__ void routing_kernel(const float* __restrict__ x,
                               const float* __restrict__ gv,
                               const float* __restrict__ go) {
    int t = blockIdx.x;
    const float* xt = x + (size_t)t * H_;
    float pv[E_], po[E_];
#pragma unroll
    for (int e = 0; e < E_; e++) { pv[e] = 0.f; po[e] = 0.f; }
    for (int k = threadIdx.x; k < H_; k += 128) {
        float xv = xt[k];
#pragma unroll
        for (int e = 0; e < E_; e++) {
            pv[e] += xv * gv[e * H_ + k];
            po[e] += xv * go[e * H_ + k];
        }
    }
    __shared__ float red[2 * E_][128];
#pragma unroll
    for (int e = 0; e < E_; e++) {
        red[e][threadIdx.x] = pv[e];
        red[E_ + e][threadIdx.x] = po[e];
    }
    __syncthreads();
    if (threadIdx.x < 2 * E_) {
        float s = 0.f;
        for (int i = 0; i < 128; i++) s += red[threadIdx.x][i];
        red[threadIdx.x][0] = s;
    }
    __syncthreads();
    if (threadIdx.x < 2) {
        bool isO = (threadIdx.x == 1);
        float sc[E_];
#pragma unroll
        for (int e = 0; e < E_; e++) {
            float d = red[(isO ? E_ : 0) + e][0];
            sc[e] = 1.f / (1.f + expf(-d));
        }
        int e0 = 0;
        for (int e = 1; e < E_; e++) if (sc[e] > sc[e0]) e0 = e;
        int e1 = -1;
        for (int e = 0; e < E_; e++) {
            if (e == e0) continue;
            if (e1 < 0 || sc[e] > sc[e1]) e1 = e;
        }
        float t1 = expf(sc[e1] - sc[e0]);
        float w0 = 1.f / (1.f + t1);
        float w1 = t1 / (1.f + t1);
        if (!isO) {
            g_wslot_v[t * 2 + 0] = w0;
            g_wslot_v[t * 2 + 1] = w1;
            int p0 = atomicAdd(&g_cnt_v[e0], 1); g_list_v[e0 * T_ + p0] = t * 2 + 0;
            int p1 = atomicAdd(&g_cnt_v[e1], 1); g_list_v[e1 * T_ + p1] = t * 2 + 1;
        } else {
            g_wslot_o[t * 2 + 0] = w0;
            g_wslot_o[t * 2 + 1] = w1;
            int p0 = atomicAdd(&g_cnt_o[e0], 1); g_list_o[e0 * T_ + p0] = t * 2 + 0;
            int p1 = atomicAdd(&g_cnt_o[e1], 1); g_list_o[e1 * T_ + p1] = t * 2 + 1;
        }
    }
}

// ---------------- launcher ----------------
extern "C" void kernel_launch(void* const* d_in, const int* in_sizes, int n_in,
                              void* d_out, int out_size) {
    const float* x      = (const float*)d_in[0];
    const float* amask  = (const float*)d_in[1];
    const float* wq     = (const float*)d_in[2];
    const float* wk     = (const float*)d_in[3];
    const float* q_a    = (const float*)d_in[4];
    const float* q_b    = (const float*)d_in[5];
    const float* k_a    = (const float*)d_in[6];
    const float* k_b    = (const float*)d_in[7];
    const float* gv     = (const float*)d_in[8];
    const float* go     = (const float*)d_in[9];
    const float* v_base = (const float*)d_in[10];
    const float* v_a    = (const float*)d_in[11];
    const float* v_b    = (const float*)d_in[12];
    const float* o_base = (const float*)d_in[13];
    const float* o_a    = (const float*)d_in[14];
    const float* o_b    = (const float*)d_in[15];
    float* out = (float*)d_out;

#define SYM(v, s) void* v; cudaGetSymbolAddress(&v, s)
    SYM(p_vt, g_vt); SYM(p_L, g_L); SYM(p_xacat, g_xacat); SYM(p_xao, g_xao);
    SYM(p_wcat, g_wcat); SYM(p_wcat2, g_wcat2);
    SYM(p_list_v, g_list_v); SYM(p_list_o, g_list_o);
    SYM(p_cnt_v, g_cnt_v); SYM(p_cnt_o, g_cnt_o);
    SYM(p_ws_v, g_wslot_v); SYM(p_ws_o, g_wslot_o);
    SYM(xs_h, g_xs_h); SYM(xs_l, g_xs_l);
    SYM(qs_h, g_qs_h); SYM(qs_l, g_qs_l);
    SYM(ks_h, g_ks_h); SYM(ks_l, g_ks_l);
    SYM(cts_h, g_cts_h); SYM(cts_l, g_cts_l);
    SYM(vts_h, g_vts_h); SYM(vts_l, g_vts_l);
    SYM(Ps_h, g_Ps_h); SYM(Ps_l, g_Ps_l);
    SYM(wqs_h, g_wqs_h); SYM(wqs_l, g_wqs_l);
    SYM(wks_h, g_wks_h); SYM(wks_l, g_wks_l);
    SYM(vbs_h, g_vbs_h); SYM(vbs_l, g_vbs_l);
    SYM(obs_h, g_obs_h); SYM(obs_l, g_obs_l);
    SYM(wcs_h, g_wcs_h); SYM(wcs_l, g_wcs_l);
    SYM(wcs2_h, g_wcs2_h); SYM(wcs2_l, g_wcs2_l);
#undef SYM

    cudaFuncSetAttribute(tc_gemm<M_XA>,     cudaFuncAttributeMaxDynamicSharedMemorySize, SMEM_SZ);
    cudaFuncSetAttribute(tc_gemm<M_MOE>,    cudaFuncAttributeMaxDynamicSharedMemorySize, SMEM_SZ);
    cudaFuncSetAttribute(tc_gemm<M_QKV>,    cudaFuncAttributeMaxDynamicSharedMemorySize, SMEM_SZ);
    cudaFuncSetAttribute(tc_gemm<M_SCORES>, cudaFuncAttributeMaxDynamicSharedMemorySize, SMEM_SZ);
    cudaFuncSetAttribute(tc_gemm<M_CTX>,    cudaFuncAttributeMaxDynamicSharedMemorySize, SMEM_SZ);

    // LoRA-A weight concats (fp32)
    cudaMemcpyAsync((float*)p_wcat,           q_a, sizeof(float) * R_ * H_,      cudaMemcpyDeviceToDevice);
    cudaMemcpyAsync((float*)p_wcat + 16 * H_, k_a, sizeof(float) * R_ * H_,      cudaMemcpyDeviceToDevice);
    cudaMemcpyAsync((float*)p_wcat + 32 * H_, v_a, sizeof(float) * E_ * R_ * H_, cudaMemcpyDeviceToDevice);
    cudaMemcpyAsync((float*)p_wcat2,          o_a, sizeof(float) * E_ * R_ * H_, cudaMemcpyDeviceToDevice);

    cudaMemsetAsync(p_vt, 0, sizeof(float) * (size_t)T_ * H_);
    cudaMemsetAsync(p_L, 0, sizeof(float) * (size_t)B_ * NH_ * S_);
    cudaMemsetAsync(out, 0, sizeof(float) * (size_t)T_ * H_);
    init_counts_kernel<<<1, 32>>>();
    routing_kernel<<<T_, 128>>>(x, gv, go);

    // splits: inputs + weights
    split_kernel<<<1024, 256>>>((const float4*)x,      (u32*)xs_h,  (u32*)xs_l,  T_ * H_ / 4);
    split_kernel<<<1024, 256>>>((const float4*)wq,     (u32*)wqs_h, (u32*)wqs_l, H_ * H_ / 4);
    split_kernel<<<1024, 256>>>((const float4*)wk,     (u32*)wks_h, (u32*)wks_l, H_ * H_ / 4);
    split_kernel<<<2048, 256>>>((const float4*)v_base, (u32*)vbs_h, (u32*)vbs_l, E_ * H_ * H_ / 4);
    split_kernel<<<2048, 256>>>((const float4*)o_base, (u32*)obs_h, (u32*)obs_l, E_ * H_ * H_ / 4);
    split_kernel<<<256, 256>>>((const float4*)p_wcat,  (u32*)wcs_h, (u32*)wcs_l, 128 * H_ / 4);
    split_kernel<<<256, 256>>>((const float4*)p_wcat2, (u32*)wcs2_h, (u32*)wcs2_l, 128 * H_ / 4);

    // XA: xacat = x @ wcat^T (fp32 out)
    tc_gemm<M_XA><<<dim3(1, T_ / 128), 256, SMEM_SZ>>>(
        (cbf*)xs_h, (cbf*)xs_l, (cbf*)wcs_h, (cbf*)wcs_l,
        (float*)p_xacat, nullptr, nullptr, nullptr, nullptr, nullptr, nullptr, nullptr,
        nullptr, nullptr);

    // fused Q-proj (z=0), K-proj (z=1), V-MoE (z=2..7, untransposed atomic V)
    tc_gemm<M_QKV><<<dim3(H_ / 128, T_ / 128, 2 + E_), 256, SMEM_SZ>>>(
        nullptr, nullptr, nullptr, nullptr,
        nullptr, nullptr, nullptr,
        nullptr, q_b,
        (const int*)p_list_v, (const int*)p_cnt_v, (const float*)p_ws_v,
        k_b, v_b);

    // transpose + split V -> vts planes
    tsplit_kernel<<<dim3(H_ / 32, S_ / 32, B_), 256>>>();

    // attention: scores with fused exp + row-sum epilogue, then ctx with 1/L epilogue
    tc_gemm<M_SCORES><<<dim3(S_ / 128, S_ / 128, B_ * NH_), 256, SMEM_SZ>>>(
        (cbf*)qs_h, (cbf*)qs_l, (cbf*)ks_h, (cbf*)ks_l,
        nullptr, nullptr, nullptr, nullptr, nullptr, nullptr, nullptr, amask,
        nullptr, nullptr);
    tc_gemm<M_CTX><<<dim3(1, S_ / 128, B_ * NH_), 256, SMEM_SZ>>>(
        (cbf*)Ps_h, (cbf*)Ps_l, (cbf*)vts_h, (cbf*)vts_l,
        nullptr, (u32*)cts_h, (u32*)cts_l, nullptr, nullptr, nullptr, nullptr, nullptr,
        nullptr, nullptr);

    // O path
    tc_gemm<M_XA><<<dim3(1, T_ / 128), 256, SMEM_SZ>>>(
        (cbf*)cts_h, (cbf*)cts_l, (cbf*)wcs2_h, (cbf*)wcs2_l,
        (float*)p_xao, nullptr, nullptr, nullptr, nullptr, nullptr, nullptr, nullptr,
        nullptr, nullptr);
    tc_gemm<M_MOE><<<dim3(H_ / 128, T_ / 128, E_), 256, SMEM_SZ>>>(
        (cbf*)cts_h, (cbf*)cts_l, (cbf*)obs_h, (cbf*)obs_l,
        out, nullptr, nullptr, (const float*)p_xao, o_b,
        (const int*)p_list_o, (const int*)p_cnt_o, (const float*)p_ws_o,
        nullptr, nullptr);
}